// round 4
// baseline (speedup 1.0000x reference)
#include <cuda_runtime.h>
#include <cuda_bf16.h>
#include <math.h>
#include <stdint.h>

#define BATCH 2
#define SEQ   2048
#define DIM   2048
#define NH    16
#define NKV   4
#define HD    128
#define MROWS (BATCH*SEQ)   /* 4096 */
#define KVDIM (NKV*HD)      /* 512  */

// tcgen05 is arch-SPECIFIC: only legal in the compute_103a pass.
#if defined(__CUDA_ARCH__) && defined(__CUDA_ARCH_FEAT_SM103_ALL)
#define HAVE_TC 1
#else
#define HAVE_TC 0
#endif

// ---------------- scratch --------------------------------------------------
__device__ float g_q [MROWS*DIM];
__device__ float g_k [MROWS*KVDIM];
__device__ float g_v [MROWS*KVDIM];
__device__ float g_ao[MROWS*DIM];

#if HAVE_TC
// ---------------- PTX helpers ----------------------------------------------
__device__ __forceinline__ uint32_t smem_u32(const void* p) {
    uint32_t a;
    asm("{ .reg .u64 t; cvta.to.shared.u64 t, %1; cvt.u32.u64 %0, t; }"
        : "=r"(a) : "l"(p));
    return a;
}
__device__ __forceinline__ uint32_t elect_one() {
    uint32_t pred;
    asm volatile("{ .reg .pred p; elect.sync _|p, 0xFFFFFFFF; selp.b32 %0,1,0,p; }"
                 : "=r"(pred));
    return pred;
}
#define MBARRIER_INIT(addr, cnt) \
    asm volatile("mbarrier.init.shared.b64 [%0], %1;" :: "r"(addr), "r"(cnt) : "memory")
#define MBARRIER_WAIT_PARITY(addr, par) do {                                   \
    uint32_t _m = (addr), _p = (par), _d;                                      \
    asm volatile("{ .reg .pred p; mbarrier.try_wait.parity.acquire.cta.shared::cta.b64 p, [%1], %2; selp.b32 %0,1,0,p; }" \
                 : "=r"(_d) : "r"(_m), "r"(_p) : "memory");                    \
    if (!_d) {                                                                 \
        asm volatile("{ .reg .pred P1; WL_%=: mbarrier.try_wait.parity.acquire.cta.shared::cta.b64 P1, [%0], %1, 0x989680; @P1 bra.uni WD_%=; bra.uni WL_%=; WD_%=: }" \
                     :: "r"(_m), "r"(_p) : "memory");                          \
    }                                                                          \
} while (0)
#define TCGEN05_ALLOC(res, n) \
    asm volatile("tcgen05.alloc.cta_group::1.sync.aligned.shared::cta.b32 [%0], %1;" \
                 :: "r"(res), "r"(n) : "memory")
#define TCGEN05_DEALLOC(t, n) \
    asm volatile("tcgen05.dealloc.cta_group::1.sync.aligned.b32 %0, %1;" :: "r"(t), "r"(n))
#define TCGEN05_RELINQ() \
    asm volatile("tcgen05.relinquish_alloc_permit.cta_group::1.sync.aligned;")
#define TCGEN05_COMMIT(mb) \
    asm volatile("tcgen05.commit.cta_group::1.mbarrier::arrive::one.shared::cluster.b64 [%0];" \
                 :: "r"(mb) : "memory")
#define TCGEN05_FENCE_AFTER() asm volatile("tcgen05.fence::after_thread_sync;" ::: "memory")
#define TCGEN05_WAIT_LD()     asm volatile("tcgen05.wait::ld.sync.aligned;" ::: "memory")
#define FENCE_ASYNC_SHARED()  asm volatile("fence.proxy.async.shared::cta;" ::: "memory")
#define TCGEN05_LD_X32(r, a)                                                   \
    asm volatile("tcgen05.ld.sync.aligned.32x32b.x32.b32 "                     \
        "{%0,%1,%2,%3,%4,%5,%6,%7,%8,%9,%10,%11,%12,%13,%14,%15,"              \
        "%16,%17,%18,%19,%20,%21,%22,%23,%24,%25,%26,%27,%28,%29,%30,%31}, [%32];" \
        : "=r"((r)[0]),"=r"((r)[1]),"=r"((r)[2]),"=r"((r)[3]),                 \
          "=r"((r)[4]),"=r"((r)[5]),"=r"((r)[6]),"=r"((r)[7]),                 \
          "=r"((r)[8]),"=r"((r)[9]),"=r"((r)[10]),"=r"((r)[11]),               \
          "=r"((r)[12]),"=r"((r)[13]),"=r"((r)[14]),"=r"((r)[15]),             \
          "=r"((r)[16]),"=r"((r)[17]),"=r"((r)[18]),"=r"((r)[19]),             \
          "=r"((r)[20]),"=r"((r)[21]),"=r"((r)[22]),"=r"((r)[23]),             \
          "=r"((r)[24]),"=r"((r)[25]),"=r"((r)[26]),"=r"((r)[27]),             \
          "=r"((r)[28]),"=r"((r)[29]),"=r"((r)[30]),"=r"((r)[31])              \
        : "r"(a))

// SW128 K-major descriptor: layout=2, version=1, SBO=64, LBO=1
__device__ __forceinline__ uint64_t make_desc(uint32_t addr) {
    return ( (uint64_t)2u << 61 ) | ( (uint64_t)1u << 46 )
         | ( (uint64_t)64u << 32 ) | ( (uint64_t)1u << 16 )
         | ( (uint64_t)(addr >> 4) & 0x3FFFu );
}
__device__ __forceinline__ void mma_f16_ss(uint32_t d, uint64_t a, uint64_t b,
                                           uint32_t idesc, uint32_t en) {
    asm volatile("{ .reg .pred p; setp.ne.u32 p, %5, 0;\n\t"
        "tcgen05.mma.cta_group::1.kind::f16 [%0], %1, %2, %3, {%4,%4,%4,%4}, p; }"
        :: "r"(d), "l"(a), "l"(b), "r"(idesc), "r"(0u), "r"(en) : "memory");
}
// idesc kind::f16: dtype=F32, atype=BF16, btype=BF16, N=128, M=128
#define GEMM_IDESC (0x490u | (16u << 17) | (8u << 24))
#endif // HAVE_TC

__device__ __forceinline__ uint32_t swz(uint32_t off) {
    return off ^ ((off >> 3) & 0x70u);
}

// ---------------- GEMM: C[M,N] = A[M,K] @ B[K,N], fp32 ---------------------
// grid (N/128, M/128), 256 threads, dynamic smem GEMM_SMEM.
// 103a pass: tcgen05 bf16x3.  base pass: classic FFMA 8x8 microtile fallback.
#define GEMM_SMEM (1024 + 1024 + 2*65536)

__global__ __launch_bounds__(256) void gemm_tc(const float* __restrict__ A,
                                               const float* __restrict__ B,
                                               float* __restrict__ C,
                                               int N, int K) {
#if HAVE_TC
    extern __shared__ char smem[];
    const uint32_t sb   = smem_u32(smem);
    const uint32_t base = (sb + 1023u) & ~1023u;
    const uint32_t hdr  = base;          // [0]=tmem ptr, [16],[24]=mbar0/1
    const uint32_t tile = base + 1024;
    char* tp = smem + (tile - sb);

    const int tid  = threadIdx.x;
    const int wid  = tid >> 5;
    const int lane = tid & 31;
    const int m0 = blockIdx.y * 128, n0 = blockIdx.x * 128;

    if (wid == 0) TCGEN05_ALLOC(hdr, 128);
    if (tid == 0) { MBARRIER_INIT(hdr + 16, 1); MBARRIER_INIT(hdr + 24, 1); }
    __syncthreads();
    uint32_t tmem;
    asm volatile("ld.shared.b32 %0, [%1];" : "=r"(tmem) : "r"(hdr));

    const int NC = K >> 6;     // 64-wide K chunks
    for (int c = 0; c < NC; c++) {
        const int buf  = c & 1;
        const int boff = buf * 65536;
        const int k0   = c << 6;

        if (c >= 2)
            MBARRIER_WAIT_PARITY(hdr + 16 + 8 * buf, (uint32_t)(((c >> 1) - 1) & 1));

        // A chunk: 128 m-rows x 64 k -> hi/lo bf16, K-major SW128 rows
#pragma unroll
        for (int i = 0; i < 8; i++) {
            int u  = tid + i * 256;
            int m  = u >> 4, k4 = u & 15;
            float4 a = *(const float4*)(A + (size_t)(m0 + m) * K + k0 + k4 * 4);
            __nv_bfloat16 h0 = __float2bfloat16(a.x);
            __nv_bfloat16 h1 = __float2bfloat16(a.y);
            __nv_bfloat16 h2 = __float2bfloat16(a.z);
            __nv_bfloat16 h3 = __float2bfloat16(a.w);
            __nv_bfloat16 l0 = __float2bfloat16(a.x - __bfloat162float(h0));
            __nv_bfloat16 l1 = __float2bfloat16(a.y - __bfloat162float(h1));
            __nv_bfloat16 l2 = __float2bfloat16(a.z - __bfloat162float(h2));
            __nv_bfloat16 l3 = __float2bfloat16(a.w - __bfloat162float(h3));
            uint32_t off = swz((uint32_t)(m * 128 + k4 * 8));
            __nv_bfloat162 hA(h0, h1), hB(h2, h3), lA(l0, l1), lB(l2, l3);
            *(uint2*)(tp + boff + off) = make_uint2(*(uint32_t*)&hA, *(uint32_t*)&hB);
            *(uint2*)(tp + boff + 16384 + off) = make_uint2(*(uint32_t*)&lA, *(uint32_t*)&lB);
        }

        // B chunk: B^T rows n (128) x 64 k.  B^T[n][k] = B[k][n].
#pragma unroll
        for (int i = 0; i < 8; i++) {
            int u = tid + i * 256;
            int n = u & 127, k4 = u >> 7;
            const float* bp = B + (size_t)(k0 + k4 * 4) * N + n0 + n;
            float b0 = bp[0], b1 = bp[N], b2 = bp[2 * (size_t)N], b3 = bp[3 * (size_t)N];
            __nv_bfloat16 h0 = __float2bfloat16(b0);
            __nv_bfloat16 h1 = __float2bfloat16(b1);
            __nv_bfloat16 h2 = __float2bfloat16(b2);
            __nv_bfloat16 h3 = __float2bfloat16(b3);
            __nv_bfloat16 l0 = __float2bfloat16(b0 - __bfloat162float(h0));
            __nv_bfloat16 l1 = __float2bfloat16(b1 - __bfloat162float(h1));
            __nv_bfloat16 l2 = __float2bfloat16(b2 - __bfloat162float(h2));
            __nv_bfloat16 l3 = __float2bfloat16(b3 - __bfloat162float(h3));
            uint32_t off = swz((uint32_t)(n * 128 + k4 * 8));
            __nv_bfloat162 hA(h0, h1), hB(h2, h3), lA(l0, l1), lB(l2, l3);
            *(uint2*)(tp + boff + 32768 + off) = make_uint2(*(uint32_t*)&hA, *(uint32_t*)&hB);
            *(uint2*)(tp + boff + 49152 + off) = make_uint2(*(uint32_t*)&lA, *(uint32_t*)&lB);
        }

        FENCE_ASYNC_SHARED();
        __syncthreads();

        if (wid == 0 && elect_one()) {
            uint64_t ah = make_desc(tile + boff);
            uint64_t al = make_desc(tile + boff + 16384);
            uint64_t bh = make_desc(tile + boff + 32768);
            uint64_t bl = make_desc(tile + boff + 49152);
#pragma unroll
            for (int s = 0; s < 4; s++) {       // K=16 per dispatch
                uint32_t en0 = (c == 0 && s == 0) ? 0u : 1u;
                mma_f16_ss(tmem, ah + s * 2, bh + s * 2, GEMM_IDESC, en0);
                mma_f16_ss(tmem, ah + s * 2, bl + s * 2, GEMM_IDESC, 1u);
                mma_f16_ss(tmem, al + s * 2, bh + s * 2, GEMM_IDESC, 1u);
            }
            TCGEN05_COMMIT(hdr + 16 + 8 * buf);
        }
    }

    MBARRIER_WAIT_PARITY(hdr + 16 + 8 * ((NC - 1) & 1),
                         (uint32_t)(((NC - 1) >> 1) & 1));
    TCGEN05_FENCE_AFTER();

    if (wid < 4) {
        float* crow = C + (size_t)(m0 + wid * 32 + lane) * N + n0;
#pragma unroll
        for (int g = 0; g < 4; g++) {
            uint32_t r[32];
            TCGEN05_LD_X32(r, tmem + g * 32);
            TCGEN05_WAIT_LD();
            float* f = (float*)r;
#pragma unroll
            for (int q4 = 0; q4 < 8; q4++)
                *(float4*)(crow + g * 32 + q4 * 4) =
                    make_float4(f[q4 * 4], f[q4 * 4 + 1], f[q4 * 4 + 2], f[q4 * 4 + 3]);
        }
    }
    __syncthreads();
    if (wid == 0) {
        TCGEN05_RELINQ();
        TCGEN05_DEALLOC(tmem, 128);
    }
#else
    // ---------------- FFMA fallback (base sm_103 pass) ----------------------
    __shared__ float As[8][128];
    __shared__ float Bs[8][128];
    const int bx = blockIdx.x, by = blockIdx.y;
    const int tid = threadIdx.x;
    const int tx = tid & 15, ty = tid >> 4;
    const int a_row = tid >> 1;
    const int a_col = (tid & 1) * 4;
    const int b_row = tid >> 5;
    const int b_col = (tid & 31) * 4;

    const float* Ab = A + (size_t)(by * 128) * K;
    const float* Bb = B + bx * 128;

    float acc[8][8];
#pragma unroll
    for (int i = 0; i < 8; i++)
#pragma unroll
        for (int j = 0; j < 8; j++) acc[i][j] = 0.f;

    for (int k0 = 0; k0 < K; k0 += 8) {
        float4 av = *(const float4*)(Ab + (size_t)a_row * K + k0 + a_col);
        As[a_col + 0][a_row] = av.x;
        As[a_col + 1][a_row] = av.y;
        As[a_col + 2][a_row] = av.z;
        As[a_col + 3][a_row] = av.w;
        *(float4*)&Bs[b_row][b_col] =
            *(const float4*)(Bb + (size_t)(k0 + b_row) * N + b_col);
        __syncthreads();
#pragma unroll
        for (int kk = 0; kk < 8; kk++) {
            float ar[8], br[8];
            *(float4*)(ar)     = *(const float4*)&As[kk][ty * 8];
            *(float4*)(ar + 4) = *(const float4*)&As[kk][ty * 8 + 4];
            *(float4*)(br)     = *(const float4*)&Bs[kk][tx * 8];
            *(float4*)(br + 4) = *(const float4*)&Bs[kk][tx * 8 + 4];
#pragma unroll
            for (int i = 0; i < 8; i++)
#pragma unroll
                for (int j = 0; j < 8; j++)
                    acc[i][j] += ar[i] * br[j];
        }
        __syncthreads();
    }

#pragma unroll
    for (int i = 0; i < 8; i++) {
        float* Crow = C + (size_t)(by * 128 + ty * 8 + i) * N + bx * 128 + tx * 8;
        *(float4*)Crow       = make_float4(acc[i][0], acc[i][1], acc[i][2], acc[i][3]);
        *(float4*)(Crow + 4) = make_float4(acc[i][4], acc[i][5], acc[i][6], acc[i][7]);
    }
#endif
}

// ---------------- fused per-head RMSNorm + RoPE (in place) -----------------
__global__ __launch_bounds__(128) void normrope(float* __restrict__ q,
                                                float* __restrict__ k,
                                                const float* __restrict__ qw,
                                                const float* __restrict__ kw) {
    const int row = blockIdx.x;
    const int hy  = blockIdx.y;
    const int d   = threadIdx.x;
    const int s   = row & (SEQ - 1);

    float* p;
    const float* w;
    if (hy < NH) { p = q + (size_t)row * DIM   + hy * HD;        w = qw; }
    else         { p = k + (size_t)row * KVDIM + (hy - NH) * HD; w = kw; }

    float x = p[d];
    float v2 = x * x;
#pragma unroll
    for (int off = 16; off > 0; off >>= 1)
        v2 += __shfl_xor_sync(0xffffffffu, v2, off);
    __shared__ float wsum[4];
    const int lane = d & 31, wid = d >> 5;
    if (lane == 0) wsum[wid] = v2;
    __syncthreads();
    float total = wsum[0] + wsum[1] + wsum[2] + wsum[3];
    float rn = rsqrtf(total * (1.0f / 128.0f) + 1e-6f);
    float nx = x * rn * w[d];

    __shared__ float sn[128];
    sn[d] = nx;
    __syncthreads();

    const int j = d & 63;
    float invf  = (float)exp(-9.210340371976184 * ((double)(2 * j) * (1.0 / 128.0)));
    float theta = (float)s * invf;
    double td = (double)theta;
    float c  = (float)cos(td);
    float si = (float)sin(td);
    float out = (d < 64) ? (nx * c - sn[d + 64] * si)
                         : (nx * c + sn[d - 64] * si);
    p[d] = out;
}

// ---------------- flash attention, fp32, BM=64 BN=64 D=128 -----------------
#define QKV_STRIDE 132
#define P_STRIDE   65
#define RED_STRIDE 9
#define FLASH_SMEM_FLOATS (3*64*QKV_STRIDE + 64*P_STRIDE + 2*64*RED_STRIDE)

__global__ __launch_bounds__(256) void flash_attn(const float* __restrict__ q,
                                                  const float* __restrict__ k,
                                                  const float* __restrict__ v,
                                                  float* __restrict__ ao) {
    extern __shared__ float sm[];
    float* Qs   = sm;
    float* Ks   = Qs + 64 * QKV_STRIDE;
    float* Vs   = Ks + 64 * QKV_STRIDE;
    float* Ps   = Vs + 64 * QKV_STRIDE;
    float* redm = Ps + 64 * P_STRIDE;
    float* reds = redm + 64 * RED_STRIDE;

    const int qt  = blockIdx.x;
    const int h   = blockIdx.y;
    const int b   = blockIdx.z;
    const int kv  = h >> 2;
    const int tid = threadIdx.x;

    const int r0   = tid & 31;
    const int r1   = r0 + 32;
    const int tcol = tid >> 5;
    const int c0   = tcol * 8;

    const float scale = 0.08838834764831843f;

    const float* qbase = q + ((size_t)(b * SEQ + qt * 64)) * DIM + h * HD;
#pragma unroll
    for (int i = 0; i < 8; i++) {
        int lin = tid + i * 256;
        int m = lin >> 5, d4 = lin & 31;
        float4 t = *(const float4*)(qbase + (size_t)m * DIM + d4 * 4);
        t.x *= scale; t.y *= scale; t.z *= scale; t.w *= scale;
        *(float4*)(Qs + m * QKV_STRIDE + d4 * 4) = t;
    }

    float mi0 = -1e30f, mi1 = -1e30f, li0 = 0.f, li1 = 0.f;
    float o0[16], o1[16];
#pragma unroll
    for (int i = 0; i < 16; i++) { o0[i] = 0.f; o1[i] = 0.f; }

    const float* kbase = k + (size_t)(b * SEQ) * KVDIM + kv * HD;
    const float* vbase = v + (size_t)(b * SEQ) * KVDIM + kv * HD;

    for (int kt = 0; kt < SEQ / 64; kt++) {
        const float* kb = kbase + (size_t)(kt * 64) * KVDIM;
        const float* vb = vbase + (size_t)(kt * 64) * KVDIM;
#pragma unroll
        for (int i = 0; i < 8; i++) {
            int lin = tid + i * 256;
            int n = lin >> 5, d4 = lin & 31;
            *(float4*)(Ks + n * QKV_STRIDE + d4 * 4) =
                *(const float4*)(kb + (size_t)n * KVDIM + d4 * 4);
            *(float4*)(Vs + n * QKV_STRIDE + d4 * 4) =
                *(const float4*)(vb + (size_t)n * KVDIM + d4 * 4);
        }
        __syncthreads();

        float acc0[8], acc1[8];
#pragma unroll
        for (int j = 0; j < 8; j++) { acc0[j] = 0.f; acc1[j] = 0.f; }
        const float4* q0p = (const float4*)(Qs + r0 * QKV_STRIDE);
        const float4* q1p = (const float4*)(Qs + r1 * QKV_STRIDE);
#pragma unroll 4
        for (int d4 = 0; d4 < 32; d4++) {
            float4 a0 = q0p[d4], a1 = q1p[d4];
#pragma unroll
            for (int j = 0; j < 8; j++) {
                float4 kk4 = *(const float4*)(Ks + (c0 + j) * QKV_STRIDE + d4 * 4);
                acc0[j] += a0.x * kk4.x; acc0[j] += a0.y * kk4.y;
                acc0[j] += a0.z * kk4.z; acc0[j] += a0.w * kk4.w;
                acc1[j] += a1.x * kk4.x; acc1[j] += a1.y * kk4.y;
                acc1[j] += a1.z * kk4.z; acc1[j] += a1.w * kk4.w;
            }
        }

        float pm0 = acc0[0], pm1 = acc1[0];
#pragma unroll
        for (int j = 1; j < 8; j++) { pm0 = fmaxf(pm0, acc0[j]); pm1 = fmaxf(pm1, acc1[j]); }
        redm[r0 * RED_STRIDE + tcol] = pm0;
        redm[r1 * RED_STRIDE + tcol] = pm1;
        __syncthreads();

        float mt0 = redm[r0 * RED_STRIDE], mt1 = redm[r1 * RED_STRIDE];
#pragma unroll
        for (int jj = 1; jj < 8; jj++) {
            mt0 = fmaxf(mt0, redm[r0 * RED_STRIDE + jj]);
            mt1 = fmaxf(mt1, redm[r1 * RED_STRIDE + jj]);
        }
        float mn0 = fmaxf(mi0, mt0), mn1 = fmaxf(mi1, mt1);

        float s0 = 0.f, s1 = 0.f;
#pragma unroll
        for (int j = 0; j < 8; j++) {
            float p0v = __expf(acc0[j] - mn0);
            float p1v = __expf(acc1[j] - mn1);
            Ps[r0 * P_STRIDE + c0 + j] = p0v;
            Ps[r1 * P_STRIDE + c0 + j] = p1v;
            s0 += p0v; s1 += p1v;
        }
        reds[r0 * RED_STRIDE + tcol] = s0;
        reds[r1 * RED_STRIDE + tcol] = s1;
        __syncthreads();

        float ls0 = 0.f, ls1 = 0.f;
#pragma unroll
        for (int jj = 0; jj < 8; jj++) {
            ls0 += reds[r0 * RED_STRIDE + jj];
            ls1 += reds[r1 * RED_STRIDE + jj];
        }
        float al0 = __expf(mi0 - mn0), al1 = __expf(mi1 - mn1);
        li0 = li0 * al0 + ls0; mi0 = mn0;
        li1 = li1 * al1 + ls1; mi1 = mn1;

#pragma unroll
        for (int i = 0; i < 16; i++) { o0[i] *= al0; o1[i] *= al1; }
#pragma unroll 2
        for (int j = 0; j < 64; j++) {
            float p0v = Ps[r0 * P_STRIDE + j];
            float p1v = Ps[r1 * P_STRIDE + j];
            const float4* vp = (const float4*)(Vs + j * QKV_STRIDE + tcol * 16);
#pragma unroll
            for (int i4 = 0; i4 < 4; i4++) {
                float4 vv = vp[i4];
                o0[i4 * 4 + 0] += p0v * vv.x; o0[i4 * 4 + 1] += p0v * vv.y;
                o0[i4 * 4 + 2] += p0v * vv.z; o0[i4 * 4 + 3] += p0v * vv.w;
                o1[i4 * 4 + 0] += p1v * vv.x; o1[i4 * 4 + 1] += p1v * vv.y;
                o1[i4 * 4 + 2] += p1v * vv.z; o1[i4 * 4 + 3] += p1v * vv.w;
            }
        }
        __syncthreads();
    }

    float inv0 = 1.f / li0, inv1 = 1.f / li1;
    float* aob = ao + ((size_t)(b * SEQ + qt * 64)) * DIM + h * HD + tcol * 16;
#pragma unroll
    for (int i4 = 0; i4 < 4; i4++) {
        *(float4*)(aob + (size_t)r0 * DIM + i4 * 4) =
            make_float4(o0[i4*4+0]*inv0, o0[i4*4+1]*inv0, o0[i4*4+2]*inv0, o0[i4*4+3]*inv0);
        *(float4*)(aob + (size_t)r1 * DIM + i4 * 4) =
            make_float4(o1[i4*4+0]*inv1, o1[i4*4+1]*inv1, o1[i4*4+2]*inv1, o1[i4*4+3]*inv1);
    }
}

// -----------------------------------------------------------------------------
extern "C" void kernel_launch(void* const* d_in, const int* in_sizes, int n_in,
                              void* d_out, int out_size) {
    const float* x   = (const float*)d_in[0];
    const float* Wq  = (const float*)d_in[1];
    const float* Wk  = (const float*)d_in[2];
    const float* Wv  = (const float*)d_in[3];
    const float* Wo  = (const float*)d_in[4];
    const float* qnw = (const float*)d_in[5];
    const float* knw = (const float*)d_in[6];
    float* out = (float*)d_out;

    float *q, *k, *v, *ao;
    cudaGetSymbolAddress((void**)&q,  g_q);
    cudaGetSymbolAddress((void**)&k,  g_k);
    cudaGetSymbolAddress((void**)&v,  g_v);
    cudaGetSymbolAddress((void**)&ao, g_ao);

    const int flash_smem = FLASH_SMEM_FLOATS * (int)sizeof(float);
    cudaFuncSetAttribute(flash_attn, cudaFuncAttributeMaxDynamicSharedMemorySize,
                         flash_smem);
    cudaFuncSetAttribute(gemm_tc, cudaFuncAttributeMaxDynamicSharedMemorySize,
                         GEMM_SMEM);

    dim3 gq(DIM / 128,   MROWS / 128);   // 16 x 32
    dim3 gk(KVDIM / 128, MROWS / 128);   // 4 x 32
    gemm_tc<<<gq, 256, GEMM_SMEM>>>(x, Wq, q, DIM,   DIM);
    gemm_tc<<<gk, 256, GEMM_SMEM>>>(x, Wk, k, KVDIM, DIM);
    gemm_tc<<<gk, 256, GEMM_SMEM>>>(x, Wv, v, KVDIM, DIM);

    normrope<<<dim3(MROWS, NH + NKV), 128>>>(q, k, qnw, knw);

    flash_attn<<<dim3(SEQ / 64, NH, BATCH), 256, flash_smem>>>(q, k, v, ao);

    gemm_tc<<<gq, 256, GEMM_SMEM>>>(ao, Wo, out, DIM, DIM);
}

// round 5
// speedup vs baseline: 1.2668x; 1.2668x over previous
#include <cuda_runtime.h>
#include <cuda_bf16.h>
#include <math.h>
#include <stdint.h>

#define BATCH 2
#define SEQ   2048
#define DIM   2048
#define NH    16
#define NKV   4
#define HD    128
#define MROWS (BATCH*SEQ)
#define KVDIM (NKV*HD)

#if defined(__CUDA_ARCH__) && defined(__CUDA_ARCH_FEAT_SM103_ALL)
#define HAVE_TC 1
#else
#define HAVE_TC 0
#endif

// ---------------- scratch ---------------------------------------------------
__device__ float g_q [MROWS*DIM];
__device__ float g_k [MROWS*KVDIM];
__device__ float g_v [MROWS*KVDIM];
__device__ float g_ao[MROWS*DIM];
__device__ __nv_bfloat16 g_xh [MROWS*DIM],   g_xl [MROWS*DIM];
__device__ __nv_bfloat16 g_aoh[MROWS*DIM],   g_aol[MROWS*DIM];
__device__ __nv_bfloat16 g_wqh[DIM*DIM],     g_wql[DIM*DIM];
__device__ __nv_bfloat16 g_wkh[KVDIM*DIM],   g_wkl[KVDIM*DIM];
__device__ __nv_bfloat16 g_wvh[KVDIM*DIM],   g_wvl[KVDIM*DIM];
__device__ __nv_bfloat16 g_woh[DIM*DIM],     g_wol[DIM*DIM];
__device__ __nv_bfloat16 g_qbh[MROWS*DIM],   g_qbl[MROWS*DIM];
__device__ __nv_bfloat16 g_kbh[MROWS*KVDIM], g_kbl[MROWS*KVDIM];
__device__ __nv_bfloat16 g_vth[MROWS*KVDIM], g_vtl[MROWS*KVDIM]; // V^T [b][kv][d][s]

__device__ __forceinline__ uint32_t swz(uint32_t off) {
    return off ^ ((off >> 3) & 0x70u);
}

#if HAVE_TC
__device__ __forceinline__ uint32_t smem_u32(const void* p) {
    uint32_t a;
    asm("{ .reg .u64 t; cvta.to.shared.u64 t, %1; cvt.u32.u64 %0, t; }" : "=r"(a) : "l"(p));
    return a;
}
__device__ __forceinline__ uint32_t elect_one() {
    uint32_t pred;
    asm volatile("{ .reg .pred p; elect.sync _|p, 0xFFFFFFFF; selp.b32 %0,1,0,p; }" : "=r"(pred));
    return pred;
}
#define MBARRIER_INIT(addr, cnt) \
    asm volatile("mbarrier.init.shared.b64 [%0], %1;" :: "r"(addr), "r"(cnt) : "memory")
#define MBARRIER_WAIT_PARITY(addr, par) do {                                   \
    uint32_t _m = (addr), _p = (par), _d;                                      \
    asm volatile("{ .reg .pred p; mbarrier.try_wait.parity.acquire.cta.shared::cta.b64 p, [%1], %2; selp.b32 %0,1,0,p; }" \
                 : "=r"(_d) : "r"(_m), "r"(_p) : "memory");                    \
    if (!_d) {                                                                 \
        asm volatile("{ .reg .pred P1; WL_%=: mbarrier.try_wait.parity.acquire.cta.shared::cta.b64 P1, [%0], %1, 0x989680; @P1 bra.uni WD_%=; bra.uni WL_%=; WD_%=: }" \
                     :: "r"(_m), "r"(_p) : "memory");                          \
    }                                                                          \
} while (0)
#define TCGEN05_ALLOC(res, n) \
    asm volatile("tcgen05.alloc.cta_group::1.sync.aligned.shared::cta.b32 [%0], %1;" :: "r"(res), "r"(n) : "memory")
#define TCGEN05_DEALLOC(t, n) \
    asm volatile("tcgen05.dealloc.cta_group::1.sync.aligned.b32 %0, %1;" :: "r"(t), "r"(n))
#define TCGEN05_RELINQ() \
    asm volatile("tcgen05.relinquish_alloc_permit.cta_group::1.sync.aligned;")
#define TCGEN05_COMMIT(mb) \
    asm volatile("tcgen05.commit.cta_group::1.mbarrier::arrive::one.shared::cluster.b64 [%0];" :: "r"(mb) : "memory")
#define TCGEN05_FENCE_BEFORE() asm volatile("tcgen05.fence::before_thread_sync;" ::: "memory")
#define TCGEN05_FENCE_AFTER()  asm volatile("tcgen05.fence::after_thread_sync;" ::: "memory")
#define TCGEN05_WAIT_LD()      asm volatile("tcgen05.wait::ld.sync.aligned;" ::: "memory")
#define TCGEN05_WAIT_ST()      asm volatile("tcgen05.wait::st.sync.aligned;" ::: "memory")
#define FENCE_ASYNC_SHARED()   asm volatile("fence.proxy.async.shared::cta;" ::: "memory")
#define TCGEN05_LD_X32(r, a)                                                   \
    asm volatile("tcgen05.ld.sync.aligned.32x32b.x32.b32 "                     \
        "{%0,%1,%2,%3,%4,%5,%6,%7,%8,%9,%10,%11,%12,%13,%14,%15,"              \
        "%16,%17,%18,%19,%20,%21,%22,%23,%24,%25,%26,%27,%28,%29,%30,%31}, [%32];" \
        : "=r"((r)[0]),"=r"((r)[1]),"=r"((r)[2]),"=r"((r)[3]),                 \
          "=r"((r)[4]),"=r"((r)[5]),"=r"((r)[6]),"=r"((r)[7]),                 \
          "=r"((r)[8]),"=r"((r)[9]),"=r"((r)[10]),"=r"((r)[11]),               \
          "=r"((r)[12]),"=r"((r)[13]),"=r"((r)[14]),"=r"((r)[15]),             \
          "=r"((r)[16]),"=r"((r)[17]),"=r"((r)[18]),"=r"((r)[19]),             \
          "=r"((r)[20]),"=r"((r)[21]),"=r"((r)[22]),"=r"((r)[23]),             \
          "=r"((r)[24]),"=r"((r)[25]),"=r"((r)[26]),"=r"((r)[27]),             \
          "=r"((r)[28]),"=r"((r)[29]),"=r"((r)[30]),"=r"((r)[31])              \
        : "r"(a))
#define TCGEN05_ST_X16(a, r)                                                   \
    asm volatile("tcgen05.st.sync.aligned.32x32b.x16.b32 [%0], "               \
        "{%1,%2,%3,%4,%5,%6,%7,%8,%9,%10,%11,%12,%13,%14,%15,%16};"            \
        :: "r"(a),                                                             \
           "r"((r)[0]),"r"((r)[1]),"r"((r)[2]),"r"((r)[3]),                    \
           "r"((r)[4]),"r"((r)[5]),"r"((r)[6]),"r"((r)[7]),                    \
           "r"((r)[8]),"r"((r)[9]),"r"((r)[10]),"r"((r)[11]),                  \
           "r"((r)[12]),"r"((r)[13]),"r"((r)[14]),"r"((r)[15])                 \
        : "memory")

__device__ __forceinline__ uint64_t make_desc(uint32_t addr) {
    return ((uint64_t)2u << 61) | ((uint64_t)1u << 46)
         | ((uint64_t)64u << 32) | ((uint64_t)1u << 16)
         | ((uint64_t)(addr >> 4) & 0x3FFFu);
}
__device__ __forceinline__ void mma_f16_ss(uint32_t d, uint64_t a, uint64_t b,
                                           uint32_t idesc, uint32_t en) {
    asm volatile("{ .reg .pred p; setp.ne.u32 p, %5, 0;\n\t"
        "tcgen05.mma.cta_group::1.kind::f16 [%0], %1, %2, %3, {%4,%4,%4,%4}, p; }"
        :: "r"(d), "l"(a), "l"(b), "r"(idesc), "r"(0u), "r"(en) : "memory");
}
__device__ __forceinline__ void mma_f16_ts(uint32_t d, uint32_t a, uint64_t b,
                                           uint32_t idesc, uint32_t en) {
    asm volatile("{ .reg .pred p; setp.ne.u32 p, %5, 0;\n\t"
        "tcgen05.mma.cta_group::1.kind::f16 [%0], [%1], %2, %3, {%4,%4,%4,%4}, p; }"
        :: "r"(d), "r"(a), "l"(b), "r"(idesc), "r"(0u), "r"(en) : "memory");
}
#define GEMM_IDESC (0x490u | (16u << 17) | (8u << 24))  // F32 acc, bf16, M=128, N=128
#endif // HAVE_TC

// ---------------- one-shot converters ---------------------------------------
__global__ __launch_bounds__(256) void cvt32(const float* __restrict__ in,
                                             __nv_bfloat16* __restrict__ hi,
                                             __nv_bfloat16* __restrict__ lo, int n4) {
    int i = blockIdx.x * 256 + threadIdx.x;
    if (i >= n4) return;
    float4 v = *(const float4*)(in + (size_t)i * 4);
    __nv_bfloat16 h0 = __float2bfloat16(v.x), h1 = __float2bfloat16(v.y);
    __nv_bfloat16 h2 = __float2bfloat16(v.z), h3 = __float2bfloat16(v.w);
    __nv_bfloat162 hA(h0, h1), hB(h2, h3);
    __nv_bfloat162 lA(__float2bfloat16(v.x - __bfloat162float(h0)),
                      __float2bfloat16(v.y - __bfloat162float(h1)));
    __nv_bfloat162 lB(__float2bfloat16(v.z - __bfloat162float(h2)),
                      __float2bfloat16(v.w - __bfloat162float(h3)));
    *(uint2*)(hi + (size_t)i * 4) = make_uint2(*(uint32_t*)&hA, *(uint32_t*)&hB);
    *(uint2*)(lo + (size_t)i * 4) = make_uint2(*(uint32_t*)&lA, *(uint32_t*)&lB);
}

// W [K][N] fp32 -> W^T hi/lo [N][K].  grid (N/32, K/32), block 256.
__global__ __launch_bounds__(256) void wtrans(const float* __restrict__ W,
                                              __nv_bfloat16* __restrict__ th,
                                              __nv_bfloat16* __restrict__ tl,
                                              int K, int N) {
    __shared__ float smt[32][33];
    const int n0 = blockIdx.x * 32, k0 = blockIdx.y * 32;
    const int tx = threadIdx.x & 31, ty = threadIdx.x >> 5;
#pragma unroll
    for (int i = 0; i < 4; i++)
        smt[ty + 8 * i][tx] = W[(size_t)(k0 + ty + 8 * i) * N + n0 + tx];
    __syncthreads();
#pragma unroll
    for (int i = 0; i < 4; i++) {
        int nl = ty + 8 * i;
        float f = smt[tx][nl];
        __nv_bfloat16 h = __float2bfloat16(f);
        th[(size_t)(n0 + nl) * K + k0 + tx] = h;
        tl[(size_t)(n0 + nl) * K + k0 + tx] = __float2bfloat16(f - __bfloat162float(h));
    }
}

// V fp32 [b*SEQ+s][kv*HD+d] -> V^T hi/lo [b][kv][d][s]  (output-indexed)
__global__ __launch_bounds__(256) void vconv(const float* __restrict__ v,
                                             __nv_bfloat16* __restrict__ vh,
                                             __nv_bfloat16* __restrict__ vl) {
    int o = blockIdx.x * 256 + threadIdx.x;
    if (o >= MROWS * KVDIM) return;
    int s   = o & (SEQ - 1);
    int rest = o >> 11;          // (b*NKV+kv)*HD + d
    int d   = rest & (HD - 1);
    int bkv = rest >> 7;         // b*NKV+kv
    int b = bkv >> 2, kv = bkv & 3;
    float f = v[(size_t)(b * SEQ + s) * KVDIM + kv * HD + d];
    __nv_bfloat16 h = __float2bfloat16(f);
    vh[o] = h;
    vl[o] = __float2bfloat16(f - __bfloat162float(h));
}

// ---------------- GEMM: C = A @ Bt^T, preconverted bf16x3 -------------------
#define GEMM_SMEM (1024 + 2*65536)
__global__ __launch_bounds__(256) void gemm_pre(const __nv_bfloat16* __restrict__ ah,
                                                const __nv_bfloat16* __restrict__ al,
                                                const __nv_bfloat16* __restrict__ bh,
                                                const __nv_bfloat16* __restrict__ bl,
                                                float* __restrict__ C, int N, int K) {
#if HAVE_TC
    extern __shared__ char smem[];
    const uint32_t sb   = smem_u32(smem);
    const uint32_t base = (sb + 1023u) & ~1023u;
    const uint32_t hdr  = base;
    const uint32_t tile = base + 1024;
    char* tp = smem + (tile - sb);
    const int tid = threadIdx.x, wid = tid >> 5, lane = tid & 31;
    const int m0 = blockIdx.y * 128, n0 = blockIdx.x * 128;

    if (wid == 0) TCGEN05_ALLOC(hdr, 128);
    if (tid == 0) { MBARRIER_INIT(hdr + 16, 1); MBARRIER_INIT(hdr + 24, 1); }
    __syncthreads();
    uint32_t tmem;
    asm volatile("ld.shared.b32 %0, [%1];" : "=r"(tmem) : "r"(hdr));

    const int NC = K >> 6;
    for (int c = 0; c < NC; c++) {
        const int buf = c & 1, boff = buf * 65536, k0 = c << 6;
        if (c >= 2)
            MBARRIER_WAIT_PARITY(hdr + 16 + 8 * buf, (uint32_t)(((c >> 1) - 1) & 1));
#pragma unroll 4
        for (int i = 0; i < 16; i++) {
            int s = tid + (i << 8);
            int a = s >> 10, seg = s & 1023, row = seg >> 3, sg = seg & 7;
            const __nv_bfloat16* src;
            if (a == 0)      src = ah + (size_t)(m0 + row) * K + k0 + sg * 8;
            else if (a == 1) src = al + (size_t)(m0 + row) * K + k0 + sg * 8;
            else if (a == 2) src = bh + (size_t)(n0 + row) * K + k0 + sg * 8;
            else             src = bl + (size_t)(n0 + row) * K + k0 + sg * 8;
            *(uint4*)(tp + boff + a * 16384 + swz((uint32_t)(row * 128 + sg * 16))) =
                *(const uint4*)src;
        }
        FENCE_ASYNC_SHARED();
        __syncthreads();
        if (wid == 0 && elect_one()) {
            uint64_t dah = make_desc(tile + boff);
            uint64_t dal = make_desc(tile + boff + 16384);
            uint64_t dbh = make_desc(tile + boff + 32768);
            uint64_t dbl = make_desc(tile + boff + 49152);
#pragma unroll
            for (int s = 0; s < 4; s++) {
                uint32_t en0 = (c == 0 && s == 0) ? 0u : 1u;
                mma_f16_ss(tmem, dah + s * 2, dbh + s * 2, GEMM_IDESC, en0);
                mma_f16_ss(tmem, dah + s * 2, dbl + s * 2, GEMM_IDESC, 1u);
                mma_f16_ss(tmem, dal + s * 2, dbh + s * 2, GEMM_IDESC, 1u);
            }
            TCGEN05_COMMIT(hdr + 16 + 8 * buf);
        }
    }
    MBARRIER_WAIT_PARITY(hdr + 16 + 8 * ((NC - 1) & 1), (uint32_t)(((NC - 1) >> 1) & 1));
    TCGEN05_FENCE_AFTER();
    if (wid < 4) {
        float* crow = C + (size_t)(m0 + wid * 32 + lane) * N + n0;
#pragma unroll
        for (int g = 0; g < 4; g++) {
            uint32_t r[32];
            TCGEN05_LD_X32(r, tmem + g * 32);
            TCGEN05_WAIT_LD();
            float* f = (float*)r;
#pragma unroll
            for (int q4 = 0; q4 < 8; q4++)
                *(float4*)(crow + g * 32 + q4 * 4) =
                    make_float4(f[q4*4], f[q4*4+1], f[q4*4+2], f[q4*4+3]);
        }
    }
    __syncthreads();
    if (wid == 0) { TCGEN05_RELINQ(); TCGEN05_DEALLOC(tmem, 128); }
#else
    // naive fallback (never selected: 103a cubin exists)
    const int tid = threadIdx.x;
    const int m0 = blockIdx.y * 128, n0 = blockIdx.x * 128;
    for (int e = tid; e < 128 * 128; e += 256) {
        int i = e >> 7, j = e & 127;
        float acc = 0.f;
        for (int kk = 0; kk < K; kk++) {
            float av = __bfloat162float(ah[(size_t)(m0+i)*K+kk]) +
                       __bfloat162float(al[(size_t)(m0+i)*K+kk]);
            float bv = __bfloat162float(bh[(size_t)(n0+j)*K+kk]) +
                       __bfloat162float(bl[(size_t)(n0+j)*K+kk]);
            acc += av * bv;
        }
        C[(size_t)(m0 + i) * N + n0 + j] = acc;
    }
#endif
}

// ---------------- fused RMSNorm + RoPE -> bf16 hi/lo ------------------------
__global__ __launch_bounds__(128) void normrope(const float* __restrict__ q,
                                                const float* __restrict__ k,
                                                const float* __restrict__ qw,
                                                const float* __restrict__ kw,
                                                __nv_bfloat16* __restrict__ qbh,
                                                __nv_bfloat16* __restrict__ qbl,
                                                __nv_bfloat16* __restrict__ kbh,
                                                __nv_bfloat16* __restrict__ kbl) {
    const int row = blockIdx.x, hy = blockIdx.y, d = threadIdx.x;
    const int s = row & (SEQ - 1);
    const float* p;
    const float* w;
    if (hy < NH) { p = q + (size_t)row * DIM   + hy * HD;        w = qw; }
    else         { p = k + (size_t)row * KVDIM + (hy - NH) * HD; w = kw; }

    float x = p[d];
    float v2 = x * x;
#pragma unroll
    for (int off = 16; off > 0; off >>= 1)
        v2 += __shfl_xor_sync(0xffffffffu, v2, off);
    __shared__ float wsum[4];
    const int lane = d & 31, wrp = d >> 5;
    if (lane == 0) wsum[wrp] = v2;
    __syncthreads();
    float total = wsum[0] + wsum[1] + wsum[2] + wsum[3];
    float rn = rsqrtf(total * (1.0f / 128.0f) + 1e-6f);
    float nx = x * rn * w[d];
    __shared__ float sn[128];
    sn[d] = nx;
    __syncthreads();

    const int j = d & 63;
    float invf  = (float)exp(-9.210340371976184 * ((double)(2 * j) * (1.0 / 128.0)));
    float theta = (float)s * invf;
    double td = (double)theta;
    float c  = (float)cos(td);
    float si = (float)sin(td);
    float out = (d < 64) ? (nx * c - sn[d + 64] * si)
                         : (nx * c + sn[d - 64] * si);
    if (hy < NH) {
        float o2 = out * 0.08838834764831843f;   // fold 1/sqrt(d)
        __nv_bfloat16 hh = __float2bfloat16(o2);
        size_t o = (size_t)row * DIM + hy * HD + d;
        qbh[o] = hh;
        qbl[o] = __float2bfloat16(o2 - __bfloat162float(hh));
    } else {
        __nv_bfloat16 hh = __float2bfloat16(out);
        size_t o = (size_t)row * KVDIM + (hy - NH) * HD + d;
        kbh[o] = hh;
        kbl[o] = __float2bfloat16(out - __bfloat162float(hh));
    }
}

// ---------------- flash attention on tcgen05 (no-max softmax) ---------------
// grid (SEQ/128, NH, BATCH), 256 thr.
// smem: hdr 1024 | 12 x 16KB: QH0 QH1 QL0 QL1 | KH0 KH1 KL0 KL1 | VH0 VH1 VL0 VL1
// TMEM: S@0(128), O@128(128), PH@256(64), PL@320(64)
#define FL_SMEM (1024 + 12*16384)
__global__ __launch_bounds__(256) void flash_tc(const __nv_bfloat16* __restrict__ qh,
                                                const __nv_bfloat16* __restrict__ ql,
                                                const __nv_bfloat16* __restrict__ kh,
                                                const __nv_bfloat16* __restrict__ kl,
                                                const __nv_bfloat16* __restrict__ vth,
                                                const __nv_bfloat16* __restrict__ vtl,
                                                float* __restrict__ ao) {
    const int qt = blockIdx.x, h = blockIdx.y, b = blockIdx.z;
    const int kvh = h >> 2, tid = threadIdx.x;
    const int qrow0 = b * SEQ + qt * 128;
#if HAVE_TC
    extern __shared__ char smem[];
    const uint32_t sb   = smem_u32(smem);
    const uint32_t base = (sb + 1023u) & ~1023u;
    const uint32_t hdr  = base;
    const uint32_t tile = base + 1024;
    char* tp = smem + (tile - sb);
    const int wid = tid >> 5, lane = tid & 31;

    if (wid == 0) TCGEN05_ALLOC(hdr, 512);
    if (tid == 0) { MBARRIER_INIT(hdr + 16, 1); MBARRIER_INIT(hdr + 24, 1); }
    __syncthreads();
    uint32_t tmem;
    asm volatile("ld.shared.b32 %0, [%1];" : "=r"(tmem) : "r"(hdr));
    const uint32_t S_T = tmem, O_T = tmem + 128, PH_T = tmem + 256, PL_T = tmem + 320;

    // Q tile: 4 arrays x 1024 16B-segs
#pragma unroll 4
    for (int i = 0; i < 16; i++) {
        int s = tid + (i << 8);
        int a = s >> 10, seg = s & 1023, row = seg >> 3, sg = seg & 7;
        const __nv_bfloat16* bsrc = (a & 2) ? ql : qh;
        *(uint4*)(tp + a * 16384 + swz((uint32_t)(row * 128 + sg * 16))) =
            *(const uint4*)(bsrc + (size_t)(qrow0 + row) * DIM + h * HD + (a & 1) * 64 + sg * 8);
    }
    __syncthreads();

    uint64_t dQ[4], dK[4], dV[4];
#pragma unroll
    for (int a = 0; a < 4; a++) {
        dQ[a] = make_desc(tile + a * 16384);
        dK[a] = make_desc(tile + 65536  + a * 16384);
        dV[a] = make_desc(tile + 131072 + a * 16384);
    }
    float lsum = 0.f;

    for (int kt = 0; kt < SEQ / 128; kt++) {
        const int kvrow0 = b * SEQ + kt * 128;
        // K + V^T tiles: 8 arrays x 1024 segs
#pragma unroll 4
        for (int i = 0; i < 32; i++) {
            int s = tid + (i << 8);
            int a = s >> 10, seg = s & 1023, row = seg >> 3, sg = seg & 7;
            const __nv_bfloat16* src;
            if (a < 4) {
                const __nv_bfloat16* bsrc = (a & 2) ? kl : kh;
                src = bsrc + (size_t)(kvrow0 + row) * KVDIM + kvh * HD + (a & 1) * 64 + sg * 8;
            } else {
                int aa = a - 4;
                const __nv_bfloat16* bsrc = (aa & 2) ? vtl : vth;
                src = bsrc + ((size_t)((b * NKV + kvh) * HD + row)) * SEQ
                    + kt * 128 + (aa & 1) * 64 + sg * 8;
            }
            *(uint4*)(tp + 65536 + a * 16384 + swz((uint32_t)(row * 128 + sg * 16))) =
                *(const uint4*)src;
        }
        FENCE_ASYNC_SHARED();
        __syncthreads();

        // S = Q K^T (bf16x3), accumulator reset at first dispatch
        if (wid == 0 && elect_one()) {
#pragma unroll
            for (int c = 0; c < 2; c++) {
                uint64_t qhd = dQ[c], qld = dQ[2 + c];
                uint64_t khd = dK[c], kld = dK[2 + c];
#pragma unroll
                for (int st = 0; st < 4; st++) {
                    uint32_t en0 = (c == 0 && st == 0) ? 0u : 1u;
                    mma_f16_ss(S_T, qhd + st * 2, khd + st * 2, GEMM_IDESC, en0);
                    mma_f16_ss(S_T, qhd + st * 2, kld + st * 2, GEMM_IDESC, 1u);
                    mma_f16_ss(S_T, qld + st * 2, khd + st * 2, GEMM_IDESC, 1u);
                }
            }
            TCGEN05_COMMIT(hdr + 16);
        }
        MBARRIER_WAIT_PARITY(hdr + 16, (uint32_t)(kt & 1));
        TCGEN05_FENCE_AFTER();

        // softmax (no max: |s| <= sqrt(128)), P -> TMEM as bf16 hi/lo
        if (wid < 4) {
            float sum = 0.f;
            const uint32_t woff = ((uint32_t)wid) << 21;
#pragma unroll
            for (int g = 0; g < 4; g++) {
                uint32_t r[32];
                TCGEN05_LD_X32(r, S_T + g * 32);
                TCGEN05_WAIT_LD();
                uint32_t hw[16], lw[16];
#pragma unroll
                for (int j = 0; j < 16; j++) {
                    float p0 = __expf(__uint_as_float(r[2 * j]));
                    float p1 = __expf(__uint_as_float(r[2 * j + 1]));
                    sum += p0 + p1;
                    __nv_bfloat16 h0 = __float2bfloat16(p0);
                    __nv_bfloat16 h1 = __float2bfloat16(p1);
                    __nv_bfloat162 hp(h0, h1);
                    __nv_bfloat162 lp(__float2bfloat16(p0 - __bfloat162float(h0)),
                                      __float2bfloat16(p1 - __bfloat162float(h1)));
                    hw[j] = *(uint32_t*)&hp;
                    lw[j] = *(uint32_t*)&lp;
                }
                TCGEN05_ST_X16(PH_T + g * 16 + woff, hw);
                TCGEN05_ST_X16(PL_T + g * 16 + woff, lw);
            }
            TCGEN05_WAIT_ST();
            lsum += sum;
            TCGEN05_FENCE_BEFORE();
        }
        __syncthreads();

        // O += P V   (TS: P in TMEM, V^T K-major in smem)
        if (wid == 0 && elect_one()) {
            TCGEN05_FENCE_AFTER();
#pragma unroll
            for (int c = 0; c < 2; c++) {
                uint64_t vhd = dV[c], vld = dV[2 + c];
#pragma unroll
                for (int st = 0; st < 4; st++) {
                    uint32_t aoff = c * 32 + st * 8;
                    uint32_t en0 = (kt == 0 && c == 0 && st == 0) ? 0u : 1u;
                    mma_f16_ts(O_T, PH_T + aoff, vhd + st * 2, GEMM_IDESC, en0);
                    mma_f16_ts(O_T, PH_T + aoff, vld + st * 2, GEMM_IDESC, 1u);
                    mma_f16_ts(O_T, PL_T + aoff, vhd + st * 2, GEMM_IDESC, 1u);
                }
            }
            TCGEN05_COMMIT(hdr + 24);
        }
        MBARRIER_WAIT_PARITY(hdr + 24, (uint32_t)(kt & 1));
    }

    TCGEN05_FENCE_AFTER();
    if (wid < 4) {
        float inv = 1.f / lsum;
        float* aob = ao + (size_t)(qrow0 + wid * 32 + lane) * DIM + h * HD;
#pragma unroll
        for (int g = 0; g < 4; g++) {
            uint32_t r[32];
            TCGEN05_LD_X32(r, O_T + g * 32);
            TCGEN05_WAIT_LD();
            float* f = (float*)r;
#pragma unroll
            for (int q4 = 0; q4 < 8; q4++)
                *(float4*)(aob + g * 32 + q4 * 4) =
                    make_float4(f[q4*4]*inv, f[q4*4+1]*inv, f[q4*4+2]*inv, f[q4*4+3]*inv);
        }
    }
    __syncthreads();
    if (wid == 0) { TCGEN05_RELINQ(); TCGEN05_DEALLOC(tmem, 512); }
#else
    // naive fallback (never selected)
    if (tid < 128) {
        int grow = qrow0 + tid;
        float l = 0.f;
        for (int d = 0; d < 128; d++)
            ao[(size_t)grow * DIM + h * HD + d] = 0.f;
        for (int kv = 0; kv < SEQ; kv++) {
            float s = 0.f;
            size_t ko = (size_t)(b * SEQ + kv) * KVDIM + kvh * HD;
            size_t qo = (size_t)grow * DIM + h * HD;
            for (int d = 0; d < 128; d++)
                s += (__bfloat162float(qh[qo+d]) + __bfloat162float(ql[qo+d])) *
                     (__bfloat162float(kh[ko+d]) + __bfloat162float(kl[ko+d]));
            float p = __expf(s);
            l += p;
            for (int d = 0; d < 128; d++) {
                size_t vo = ((size_t)((b * NKV + kvh) * HD + d)) * SEQ + kv;
                ao[(size_t)grow * DIM + h * HD + d] +=
                    p * (__bfloat162float(vth[vo]) + __bfloat162float(vtl[vo]));
            }
        }
        for (int d = 0; d < 128; d++)
            ao[(size_t)grow * DIM + h * HD + d] /= l;
    }
#endif
}

// -----------------------------------------------------------------------------
extern "C" void kernel_launch(void* const* d_in, const int* in_sizes, int n_in,
                              void* d_out, int out_size) {
    const float* x   = (const float*)d_in[0];
    const float* Wq  = (const float*)d_in[1];
    const float* Wk  = (const float*)d_in[2];
    const float* Wv  = (const float*)d_in[3];
    const float* Wo  = (const float*)d_in[4];
    const float* qnw = (const float*)d_in[5];
    const float* knw = (const float*)d_in[6];
    float* out = (float*)d_out;

    float *q, *k, *v, *ao;
    cudaGetSymbolAddress((void**)&q,  g_q);
    cudaGetSymbolAddress((void**)&k,  g_k);
    cudaGetSymbolAddress((void**)&v,  g_v);
    cudaGetSymbolAddress((void**)&ao, g_ao);
    __nv_bfloat16 *xh,*xl,*aoh,*aol,*wqh,*wql,*wkh,*wkl,*wvh,*wvl,*woh,*wol;
    __nv_bfloat16 *qbh,*qbl,*kbh,*kbl,*vth,*vtl;
    cudaGetSymbolAddress((void**)&xh,  g_xh);  cudaGetSymbolAddress((void**)&xl,  g_xl);
    cudaGetSymbolAddress((void**)&aoh, g_aoh); cudaGetSymbolAddress((void**)&aol, g_aol);
    cudaGetSymbolAddress((void**)&wqh, g_wqh); cudaGetSymbolAddress((void**)&wql, g_wql);
    cudaGetSymbolAddress((void**)&wkh, g_wkh); cudaGetSymbolAddress((void**)&wkl, g_wkl);
    cudaGetSymbolAddress((void**)&wvh, g_wvh); cudaGetSymbolAddress((void**)&wvl, g_wvl);
    cudaGetSymbolAddress((void**)&woh, g_woh); cudaGetSymbolAddress((void**)&wol, g_wol);
    cudaGetSymbolAddress((void**)&qbh, g_qbh); cudaGetSymbolAddress((void**)&qbl, g_qbl);
    cudaGetSymbolAddress((void**)&kbh, g_kbh); cudaGetSymbolAddress((void**)&kbl, g_kbl);
    cudaGetSymbolAddress((void**)&vth, g_vth); cudaGetSymbolAddress((void**)&vtl, g_vtl);

    cudaFuncSetAttribute(gemm_pre, cudaFuncAttributeMaxDynamicSharedMemorySize, GEMM_SMEM);
    cudaFuncSetAttribute(flash_tc, cudaFuncAttributeMaxDynamicSharedMemorySize, FL_SMEM);

    // 1. convert inputs once
    cvt32<<<(MROWS * DIM / 4 + 255) / 256, 256>>>(x, xh, xl, MROWS * DIM / 4);
    wtrans<<<dim3(DIM / 32,   DIM / 32), 256>>>(Wq, wqh, wql, DIM, DIM);
    wtrans<<<dim3(KVDIM / 32, DIM / 32), 256>>>(Wk, wkh, wkl, DIM, KVDIM);
    wtrans<<<dim3(KVDIM / 32, DIM / 32), 256>>>(Wv, wvh, wvl, DIM, KVDIM);
    wtrans<<<dim3(DIM / 32,   DIM / 32), 256>>>(Wo, woh, wol, DIM, DIM);

    // 2. projections (tcgen05 bf16x3)
    dim3 gq(DIM / 128,   MROWS / 128);
    dim3 gk(KVDIM / 128, MROWS / 128);
    gemm_pre<<<gq, 256, GEMM_SMEM>>>(xh, xl, wqh, wql, q, DIM,   DIM);
    gemm_pre<<<gk, 256, GEMM_SMEM>>>(xh, xl, wkh, wkl, k, KVDIM, DIM);
    gemm_pre<<<gk, 256, GEMM_SMEM>>>(xh, xl, wvh, wvl, v, KVDIM, DIM);

    // 3. norm + rope -> bf16 hi/lo, V transpose
    normrope<<<dim3(MROWS, NH + NKV), 128>>>(q, k, qnw, knw, qbh, qbl, kbh, kbl);
    vconv<<<(MROWS * KVDIM + 255) / 256, 256>>>(v, vth, vtl);

    // 4. flash attention (tcgen05)
    flash_tc<<<dim3(SEQ / 128, NH, BATCH), 256, FL_SMEM>>>(qbh, qbl, kbh, kbl, vth, vtl, ao);

    // 5. output projection
    cvt32<<<(MROWS * DIM / 4 + 255) / 256, 256>>>(ao, aoh, aol, MROWS * DIM / 4);
    gemm_pre<<<gq, 256, GEMM_SMEM>>>(aoh, aol, woh, wol, out, DIM, DIM);
}

// round 6
// speedup vs baseline: 1.6441x; 1.2979x over previous
#include <cuda_runtime.h>
#include <cuda_bf16.h>
#include <math.h>
#include <stdint.h>

#define BATCH 2
#define SEQ   2048
#define DIM   2048
#define NH    16
#define NKV   4
#define HD    128
#define MROWS (BATCH*SEQ)
#define KVDIM (NKV*HD)

#if defined(__CUDA_ARCH__) && defined(__CUDA_ARCH_FEAT_SM103_ALL)
#define HAVE_TC 1
#else
#define HAVE_TC 0
#endif

// ---------------- scratch ---------------------------------------------------
__device__ float g_q [MROWS*DIM];
__device__ float g_k [MROWS*KVDIM];
__device__ float g_v [MROWS*KVDIM];
__device__ float g_ao[MROWS*DIM];
__device__ __nv_bfloat16 g_xh [MROWS*DIM],   g_xl [MROWS*DIM];
__device__ __nv_bfloat16 g_aoh[MROWS*DIM],   g_aol[MROWS*DIM];
__device__ __nv_bfloat16 g_wqh[DIM*DIM],     g_wql[DIM*DIM];
__device__ __nv_bfloat16 g_wkh[KVDIM*DIM],   g_wkl[KVDIM*DIM];
__device__ __nv_bfloat16 g_wvh[KVDIM*DIM],   g_wvl[KVDIM*DIM];
__device__ __nv_bfloat16 g_woh[DIM*DIM],     g_wol[DIM*DIM];
__device__ __nv_bfloat16 g_qbh[MROWS*DIM],   g_qbl[MROWS*DIM];
__device__ __nv_bfloat16 g_kbh[MROWS*KVDIM], g_kbl[MROWS*KVDIM];
__device__ __nv_bfloat16 g_vth[MROWS*KVDIM], g_vtl[MROWS*KVDIM]; // V^T [b][kv][d][s]

__device__ __forceinline__ uint32_t swz(uint32_t off) {
    return off ^ ((off >> 3) & 0x70u);
}

#if HAVE_TC
__device__ __forceinline__ uint32_t smem_u32(const void* p) {
    uint32_t a;
    asm("{ .reg .u64 t; cvta.to.shared.u64 t, %1; cvt.u32.u64 %0, t; }" : "=r"(a) : "l"(p));
    return a;
}
__device__ __forceinline__ uint32_t elect_one() {
    uint32_t pred;
    asm volatile("{ .reg .pred p; elect.sync _|p, 0xFFFFFFFF; selp.b32 %0,1,0,p; }" : "=r"(pred));
    return pred;
}
#define MBARRIER_INIT(addr, cnt) \
    asm volatile("mbarrier.init.shared.b64 [%0], %1;" :: "r"(addr), "r"(cnt) : "memory")
#define MBARRIER_WAIT_PARITY(addr, par) do {                                   \
    uint32_t _m = (addr), _p = (par), _d;                                      \
    asm volatile("{ .reg .pred p; mbarrier.try_wait.parity.acquire.cta.shared::cta.b64 p, [%1], %2; selp.b32 %0,1,0,p; }" \
                 : "=r"(_d) : "r"(_m), "r"(_p) : "memory");                    \
    if (!_d) {                                                                 \
        asm volatile("{ .reg .pred P1; WL_%=: mbarrier.try_wait.parity.acquire.cta.shared::cta.b64 P1, [%0], %1, 0x989680; @P1 bra.uni WD_%=; bra.uni WL_%=; WD_%=: }" \
                     :: "r"(_m), "r"(_p) : "memory");                          \
    }                                                                          \
} while (0)
#define TCGEN05_ALLOC(res, n) \
    asm volatile("tcgen05.alloc.cta_group::1.sync.aligned.shared::cta.b32 [%0], %1;" :: "r"(res), "r"(n) : "memory")
#define TCGEN05_DEALLOC(t, n) \
    asm volatile("tcgen05.dealloc.cta_group::1.sync.aligned.b32 %0, %1;" :: "r"(t), "r"(n))
#define TCGEN05_RELINQ() \
    asm volatile("tcgen05.relinquish_alloc_permit.cta_group::1.sync.aligned;")
#define TCGEN05_COMMIT(mb) \
    asm volatile("tcgen05.commit.cta_group::1.mbarrier::arrive::one.shared::cluster.b64 [%0];" :: "r"(mb) : "memory")
#define TCGEN05_FENCE_BEFORE() asm volatile("tcgen05.fence::before_thread_sync;" ::: "memory")
#define TCGEN05_FENCE_AFTER()  asm volatile("tcgen05.fence::after_thread_sync;" ::: "memory")
#define TCGEN05_WAIT_LD()      asm volatile("tcgen05.wait::ld.sync.aligned;" ::: "memory")
#define TCGEN05_WAIT_ST()      asm volatile("tcgen05.wait::st.sync.aligned;" ::: "memory")
#define FENCE_ASYNC_SHARED()   asm volatile("fence.proxy.async.shared::cta;" ::: "memory")
#define TCGEN05_LD_X32(r, a)                                                   \
    asm volatile("tcgen05.ld.sync.aligned.32x32b.x32.b32 "                     \
        "{%0,%1,%2,%3,%4,%5,%6,%7,%8,%9,%10,%11,%12,%13,%14,%15,"              \
        "%16,%17,%18,%19,%20,%21,%22,%23,%24,%25,%26,%27,%28,%29,%30,%31}, [%32];" \
        : "=r"((r)[0]),"=r"((r)[1]),"=r"((r)[2]),"=r"((r)[3]),                 \
          "=r"((r)[4]),"=r"((r)[5]),"=r"((r)[6]),"=r"((r)[7]),                 \
          "=r"((r)[8]),"=r"((r)[9]),"=r"((r)[10]),"=r"((r)[11]),               \
          "=r"((r)[12]),"=r"((r)[13]),"=r"((r)[14]),"=r"((r)[15]),             \
          "=r"((r)[16]),"=r"((r)[17]),"=r"((r)[18]),"=r"((r)[19]),             \
          "=r"((r)[20]),"=r"((r)[21]),"=r"((r)[22]),"=r"((r)[23]),             \
          "=r"((r)[24]),"=r"((r)[25]),"=r"((r)[26]),"=r"((r)[27]),             \
          "=r"((r)[28]),"=r"((r)[29]),"=r"((r)[30]),"=r"((r)[31])              \
        : "r"(a))
#define TCGEN05_ST_X16(a, r)                                                   \
    asm volatile("tcgen05.st.sync.aligned.32x32b.x16.b32 [%0], "               \
        "{%1,%2,%3,%4,%5,%6,%7,%8,%9,%10,%11,%12,%13,%14,%15,%16};"            \
        :: "r"(a),                                                             \
           "r"((r)[0]),"r"((r)[1]),"r"((r)[2]),"r"((r)[3]),                    \
           "r"((r)[4]),"r"((r)[5]),"r"((r)[6]),"r"((r)[7]),                    \
           "r"((r)[8]),"r"((r)[9]),"r"((r)[10]),"r"((r)[11]),                  \
           "r"((r)[12]),"r"((r)[13]),"r"((r)[14]),"r"((r)[15])                 \
        : "memory")
#define TCGEN05_ST_X32(a, r)                                                   \
    asm volatile("tcgen05.st.sync.aligned.32x32b.x32.b32 [%0], "               \
        "{%1,%2,%3,%4,%5,%6,%7,%8,%9,%10,%11,%12,%13,%14,%15,%16,"             \
        "%17,%18,%19,%20,%21,%22,%23,%24,%25,%26,%27,%28,%29,%30,%31,%32};"    \
        :: "r"(a),                                                             \
           "r"((r)[0]),"r"((r)[1]),"r"((r)[2]),"r"((r)[3]),                    \
           "r"((r)[4]),"r"((r)[5]),"r"((r)[6]),"r"((r)[7]),                    \
           "r"((r)[8]),"r"((r)[9]),"r"((r)[10]),"r"((r)[11]),                  \
           "r"((r)[12]),"r"((r)[13]),"r"((r)[14]),"r"((r)[15]),                \
           "r"((r)[16]),"r"((r)[17]),"r"((r)[18]),"r"((r)[19]),                \
           "r"((r)[20]),"r"((r)[21]),"r"((r)[22]),"r"((r)[23]),                \
           "r"((r)[24]),"r"((r)[25]),"r"((r)[26]),"r"((r)[27]),                \
           "r"((r)[28]),"r"((r)[29]),"r"((r)[30]),"r"((r)[31])                 \
        : "memory")

__device__ __forceinline__ uint64_t make_desc(uint32_t addr) {
    return ((uint64_t)2u << 61) | ((uint64_t)1u << 46)
         | ((uint64_t)64u << 32) | ((uint64_t)1u << 16)
         | ((uint64_t)(addr >> 4) & 0x3FFFu);
}
__device__ __forceinline__ void mma_f16_ss(uint32_t d, uint64_t a, uint64_t b,
                                           uint32_t idesc, uint32_t en) {
    asm volatile("{ .reg .pred p; setp.ne.u32 p, %5, 0;\n\t"
        "tcgen05.mma.cta_group::1.kind::f16 [%0], %1, %2, %3, {%4,%4,%4,%4}, p; }"
        :: "r"(d), "l"(a), "l"(b), "r"(idesc), "r"(0u), "r"(en) : "memory");
}
__device__ __forceinline__ void mma_f16_ts(uint32_t d, uint32_t a, uint64_t b,
                                           uint32_t idesc, uint32_t en) {
    asm volatile("{ .reg .pred p; setp.ne.u32 p, %5, 0;\n\t"
        "tcgen05.mma.cta_group::1.kind::f16 [%0], [%1], %2, %3, {%4,%4,%4,%4}, p; }"
        :: "r"(d), "r"(a), "l"(b), "r"(idesc), "r"(0u), "r"(en) : "memory");
}
#define GEMM_IDESC (0x490u | (16u << 17) | (8u << 24))  // F32 acc, bf16, M=128, N=128
#endif // HAVE_TC

// ---------------- prep: 4 weight transposes + x conversion (z-sliced) -------
// grid (64, 64, 5), 256 thr.  z<4: wtrans of weight z.  z==4: cvt32 of x.
__global__ __launch_bounds__(256) void prep(const float* __restrict__ Wq,
                                            const float* __restrict__ Wk,
                                            const float* __restrict__ Wv,
                                            const float* __restrict__ Wo,
                                            const float* __restrict__ x,
                                            __nv_bfloat16* __restrict__ wqh, __nv_bfloat16* __restrict__ wql,
                                            __nv_bfloat16* __restrict__ wkh, __nv_bfloat16* __restrict__ wkl,
                                            __nv_bfloat16* __restrict__ wvh, __nv_bfloat16* __restrict__ wvl,
                                            __nv_bfloat16* __restrict__ woh, __nv_bfloat16* __restrict__ wol,
                                            __nv_bfloat16* __restrict__ xh,  __nv_bfloat16* __restrict__ xl) {
    const int z = blockIdx.z;
    const int tid = threadIdx.x;
    if (z == 4) {
        // convert x: 2M float4, 1M threads x 2
        int base = (blockIdx.y * 64 + blockIdx.x) * 256 + tid;
#pragma unroll
        for (int rep = 0; rep < 2; rep++) {
            int i = base + rep * 1048576;
            float4 v = *(const float4*)(x + (size_t)i * 4);
            __nv_bfloat16 h0 = __float2bfloat16(v.x), h1 = __float2bfloat16(v.y);
            __nv_bfloat16 h2 = __float2bfloat16(v.z), h3 = __float2bfloat16(v.w);
            __nv_bfloat162 hA(h0, h1), hB(h2, h3);
            __nv_bfloat162 lA(__float2bfloat16(v.x - __bfloat162float(h0)),
                              __float2bfloat16(v.y - __bfloat162float(h1)));
            __nv_bfloat162 lB(__float2bfloat16(v.z - __bfloat162float(h2)),
                              __float2bfloat16(v.w - __bfloat162float(h3)));
            *(uint2*)(xh + (size_t)i * 4) = make_uint2(*(uint32_t*)&hA, *(uint32_t*)&hB);
            *(uint2*)(xl + (size_t)i * 4) = make_uint2(*(uint32_t*)&lA, *(uint32_t*)&lB);
        }
        return;
    }
    const float* W;
    __nv_bfloat16 *th, *tl;
    int N;
    if      (z == 0) { W = Wq; th = wqh; tl = wql; N = DIM;   }
    else if (z == 1) { W = Wk; th = wkh; tl = wkl; N = KVDIM; }
    else if (z == 2) { W = Wv; th = wvh; tl = wvl; N = KVDIM; }
    else             { W = Wo; th = woh; tl = wol; N = DIM;   }
    const int n0 = blockIdx.x * 32, k0 = blockIdx.y * 32;
    if (n0 >= N) return;
    __shared__ float smt[32][33];
    const int tx = tid & 31, ty = tid >> 5;
#pragma unroll
    for (int i = 0; i < 4; i++)
        smt[ty + 8 * i][tx] = W[(size_t)(k0 + ty + 8 * i) * N + n0 + tx];
    __syncthreads();
#pragma unroll
    for (int i = 0; i < 4; i++) {
        int nl = ty + 8 * i;
        float f = smt[tx][nl];
        __nv_bfloat16 h = __float2bfloat16(f);
        th[(size_t)(n0 + nl) * DIM + k0 + tx] = h;
        tl[(size_t)(n0 + nl) * DIM + k0 + tx] = __float2bfloat16(f - __bfloat162float(h));
    }
}

// ---------------- cvt32 (for ao) ---------------------------------------------
__global__ __launch_bounds__(256) void cvt32(const float* __restrict__ in,
                                             __nv_bfloat16* __restrict__ hi,
                                             __nv_bfloat16* __restrict__ lo, int n4) {
    int i = blockIdx.x * 256 + threadIdx.x;
    if (i >= n4) return;
    float4 v = *(const float4*)(in + (size_t)i * 4);
    __nv_bfloat16 h0 = __float2bfloat16(v.x), h1 = __float2bfloat16(v.y);
    __nv_bfloat16 h2 = __float2bfloat16(v.z), h3 = __float2bfloat16(v.w);
    __nv_bfloat162 hA(h0, h1), hB(h2, h3);
    __nv_bfloat162 lA(__float2bfloat16(v.x - __bfloat162float(h0)),
                      __float2bfloat16(v.y - __bfloat162float(h1)));
    __nv_bfloat162 lB(__float2bfloat16(v.z - __bfloat162float(h2)),
                      __float2bfloat16(v.w - __bfloat162float(h3)));
    *(uint2*)(hi + (size_t)i * 4) = make_uint2(*(uint32_t*)&hA, *(uint32_t*)&hB);
    *(uint2*)(lo + (size_t)i * 4) = make_uint2(*(uint32_t*)&lA, *(uint32_t*)&lB);
}

// ---------------- GEMM core (bf16x3, preconverted operands) -----------------
#define GEMM_SMEM (1024 + 2*65536)
#if HAVE_TC
__device__ __forceinline__ void gemm_body(const __nv_bfloat16* ah, const __nv_bfloat16* al,
                                          const __nv_bfloat16* bh, const __nv_bfloat16* bl,
                                          float* C, int N, int K, char* smem) {
    const uint32_t sb   = smem_u32(smem);
    const uint32_t base = (sb + 1023u) & ~1023u;
    const uint32_t hdr  = base;
    const uint32_t tile = base + 1024;
    char* tp = smem + (tile - sb);
    const int tid = threadIdx.x, wid = tid >> 5, lane = tid & 31;
    const int m0 = blockIdx.y * 128, n0 = blockIdx.x * 128;

    if (wid == 0) TCGEN05_ALLOC(hdr, 128);
    if (tid == 0) { MBARRIER_INIT(hdr + 16, 1); MBARRIER_INIT(hdr + 24, 1); }
    __syncthreads();
    uint32_t tmem;
    asm volatile("ld.shared.b32 %0, [%1];" : "=r"(tmem) : "r"(hdr));

    const int NC = K >> 6;
    for (int c = 0; c < NC; c++) {
        const int buf = c & 1, boff = buf * 65536, k0 = c << 6;
        if (c >= 2)
            MBARRIER_WAIT_PARITY(hdr + 16 + 8 * buf, (uint32_t)(((c >> 1) - 1) & 1));
#pragma unroll 4
        for (int i = 0; i < 16; i++) {
            int s = tid + (i << 8);
            int a = s >> 10, seg = s & 1023, row = seg >> 3, sg = seg & 7;
            const __nv_bfloat16* src;
            if (a == 0)      src = ah + (size_t)(m0 + row) * K + k0 + sg * 8;
            else if (a == 1) src = al + (size_t)(m0 + row) * K + k0 + sg * 8;
            else if (a == 2) src = bh + (size_t)(n0 + row) * K + k0 + sg * 8;
            else             src = bl + (size_t)(n0 + row) * K + k0 + sg * 8;
            *(uint4*)(tp + boff + a * 16384 + swz((uint32_t)(row * 128 + sg * 16))) =
                *(const uint4*)src;
        }
        FENCE_ASYNC_SHARED();
        __syncthreads();
        if (wid == 0 && elect_one()) {
            uint64_t dah = make_desc(tile + boff);
            uint64_t dal = make_desc(tile + boff + 16384);
            uint64_t dbh = make_desc(tile + boff + 32768);
            uint64_t dbl = make_desc(tile + boff + 49152);
#pragma unroll
            for (int s = 0; s < 4; s++) {
                uint32_t en0 = (c == 0 && s == 0) ? 0u : 1u;
                mma_f16_ss(tmem, dah + s * 2, dbh + s * 2, GEMM_IDESC, en0);
                mma_f16_ss(tmem, dah + s * 2, dbl + s * 2, GEMM_IDESC, 1u);
                mma_f16_ss(tmem, dal + s * 2, dbh + s * 2, GEMM_IDESC, 1u);
            }
            TCGEN05_COMMIT(hdr + 16 + 8 * buf);
        }
    }
    MBARRIER_WAIT_PARITY(hdr + 16 + 8 * ((NC - 1) & 1), (uint32_t)(((NC - 1) >> 1) & 1));
    TCGEN05_FENCE_AFTER();
    if (wid < 4) {
        float* crow = C + (size_t)(m0 + wid * 32 + lane) * N + n0;
#pragma unroll
        for (int g = 0; g < 4; g++) {
            uint32_t r[32];
            TCGEN05_LD_X32(r, tmem + g * 32);
            TCGEN05_WAIT_LD();
            float* f = (float*)r;
#pragma unroll
            for (int q4 = 0; q4 < 8; q4++)
                *(float4*)(crow + g * 32 + q4 * 4) =
                    make_float4(f[q4*4], f[q4*4+1], f[q4*4+2], f[q4*4+3]);
        }
    }
    __syncthreads();
    if (wid == 0) { TCGEN05_RELINQ(); TCGEN05_DEALLOC(tmem, 128); }
}
#endif

// Q/K/V projections in one launch.  grid (16, 32, 3); z>0 uses only bx<4.
__global__ __launch_bounds__(256) void gemm_qkv(const __nv_bfloat16* __restrict__ ah,
                                                const __nv_bfloat16* __restrict__ al,
                                                const __nv_bfloat16* __restrict__ bhq,
                                                const __nv_bfloat16* __restrict__ blq,
                                                const __nv_bfloat16* __restrict__ bhk,
                                                const __nv_bfloat16* __restrict__ blk_,
                                                const __nv_bfloat16* __restrict__ bhv,
                                                const __nv_bfloat16* __restrict__ blv,
                                                float* __restrict__ cq,
                                                float* __restrict__ ck,
                                                float* __restrict__ cv) {
    const int z = blockIdx.z;
    const __nv_bfloat16 *bh, *bl;
    float* C;
    int N;
    if      (z == 0) { bh = bhq; bl = blq;  C = cq; N = DIM;   }
    else if (z == 1) { bh = bhk; bl = blk_; C = ck; N = KVDIM; }
    else             { bh = bhv; bl = blv;  C = cv; N = KVDIM; }
    if ((int)blockIdx.x * 128 >= N) return;
#if HAVE_TC
    extern __shared__ char smem[];
    gemm_body(ah, al, bh, bl, C, N, DIM, smem);
#else
    const int tid = threadIdx.x;
    const int m0 = blockIdx.y * 128, n0 = blockIdx.x * 128;
    for (int e = tid; e < 128 * 128; e += 256) {
        int i = e >> 7, j = e & 127;
        float acc = 0.f;
        for (int kk = 0; kk < DIM; kk++)
            acc += (__bfloat162float(ah[(size_t)(m0+i)*DIM+kk]) + __bfloat162float(al[(size_t)(m0+i)*DIM+kk])) *
                   (__bfloat162float(bh[(size_t)(n0+j)*DIM+kk]) + __bfloat162float(bl[(size_t)(n0+j)*DIM+kk]));
        C[(size_t)(m0 + i) * N + n0 + j] = acc;
    }
#endif
}

// plain single GEMM (for output projection)
__global__ __launch_bounds__(256) void gemm_pre(const __nv_bfloat16* __restrict__ ah,
                                                const __nv_bfloat16* __restrict__ al,
                                                const __nv_bfloat16* __restrict__ bh,
                                                const __nv_bfloat16* __restrict__ bl,
                                                float* __restrict__ C, int N, int K) {
#if HAVE_TC
    extern __shared__ char smem[];
    gemm_body(ah, al, bh, bl, C, N, K, smem);
#else
    const int tid = threadIdx.x;
    const int m0 = blockIdx.y * 128, n0 = blockIdx.x * 128;
    for (int e = tid; e < 128 * 128; e += 256) {
        int i = e >> 7, j = e & 127;
        float acc = 0.f;
        for (int kk = 0; kk < K; kk++)
            acc += (__bfloat162float(ah[(size_t)(m0+i)*K+kk]) + __bfloat162float(al[(size_t)(m0+i)*K+kk])) *
                   (__bfloat162float(bh[(size_t)(n0+j)*K+kk]) + __bfloat162float(bl[(size_t)(n0+j)*K+kk]));
        C[(size_t)(m0 + i) * N + n0 + j] = acc;
    }
#endif
}

// ---------------- normrope + V transpose (merged) ----------------------------
// grid (MROWS, 24), 128 thr.  hy<16: q head; 16..19: k head; 20..23: vconv.
__global__ __launch_bounds__(128) void normropev(const float* __restrict__ q,
                                                 const float* __restrict__ k,
                                                 const float* __restrict__ v,
                                                 const float* __restrict__ qw,
                                                 const float* __restrict__ kw,
                                                 __nv_bfloat16* __restrict__ qbh,
                                                 __nv_bfloat16* __restrict__ qbl,
                                                 __nv_bfloat16* __restrict__ kbh,
                                                 __nv_bfloat16* __restrict__ kbl,
                                                 __nv_bfloat16* __restrict__ vh,
                                                 __nv_bfloat16* __restrict__ vl) {
    const int row = blockIdx.x, hy = blockIdx.y, d = threadIdx.x;

    if (hy >= NH + NKV) {
        // V transpose slice: vb in [0, 16384)
        int vb = (hy - (NH + NKV)) * MROWS + row;
        int o = vb * 128 + d;
        int s = o & (SEQ - 1);
        int rest = o >> 11;
        int dd = rest & (HD - 1);
        int bkv = rest >> 7;
        int b = bkv >> 2, kv = bkv & 3;
        float f = v[(size_t)(b * SEQ + s) * KVDIM + kv * HD + dd];
        __nv_bfloat16 h = __float2bfloat16(f);
        vh[o] = h;
        vl[o] = __float2bfloat16(f - __bfloat162float(h));
        return;
    }

    const int s = row & (SEQ - 1);
    const float* p;
    const float* w;
    if (hy < NH) { p = q + (size_t)row * DIM   + hy * HD;        w = qw; }
    else         { p = k + (size_t)row * KVDIM + (hy - NH) * HD; w = kw; }

    float x = p[d];
    float v2 = x * x;
#pragma unroll
    for (int off = 16; off > 0; off >>= 1)
        v2 += __shfl_xor_sync(0xffffffffu, v2, off);
    __shared__ float wsum[4];
    const int lane = d & 31, wrp = d >> 5;
    if (lane == 0) wsum[wrp] = v2;
    __syncthreads();
    float total = wsum[0] + wsum[1] + wsum[2] + wsum[3];
    float rn = rsqrtf(total * (1.0f / 128.0f) + 1e-6f);
    float nx = x * rn * w[d];
    __shared__ float sn[128];
    sn[d] = nx;
    __syncthreads();

    const int j = d & 63;
    float invf  = (float)exp(-9.210340371976184 * ((double)(2 * j) * (1.0 / 128.0)));
    float theta = (float)s * invf;
    double td = (double)theta;
    float c  = (float)cos(td);
    float si = (float)sin(td);
    float out = (d < 64) ? (nx * c - sn[d + 64] * si)
                         : (nx * c + sn[d - 64] * si);
    if (hy < NH) {
        float o2 = out * 0.08838834764831843f;
        __nv_bfloat16 hh = __float2bfloat16(o2);
        size_t o = (size_t)row * DIM + hy * HD + d;
        qbh[o] = hh;
        qbl[o] = __float2bfloat16(o2 - __bfloat162float(hh));
    } else {
        __nv_bfloat16 hh = __float2bfloat16(out);
        size_t o = (size_t)row * KVDIM + (hy - NH) * HD + d;
        kbh[o] = hh;
        kbl[o] = __float2bfloat16(out - __bfloat162float(hh));
    }
}

// ---------------- flash attention, pipelined tcgen05 -------------------------
// grid (SEQ/128, NH, BATCH), 256 thr.
// smem: hdr 1024 | Kbuf0 64KB | Kbuf1 64KB | Vbuf 64KB   (each buf: H0 H1 L0 L1)
// TMEM: Q@0(128: hi 0-63, lo 64-127), S@128, O@256, PH@384, PL@448
#define FL_SMEM (1024 + 3*65536)
__global__ __launch_bounds__(256) void flash_tc(const __nv_bfloat16* __restrict__ qh,
                                                const __nv_bfloat16* __restrict__ ql,
                                                const __nv_bfloat16* __restrict__ kh,
                                                const __nv_bfloat16* __restrict__ kl,
                                                const __nv_bfloat16* __restrict__ vth,
                                                const __nv_bfloat16* __restrict__ vtl,
                                                float* __restrict__ ao) {
    const int qt = blockIdx.x, h = blockIdx.y, b = blockIdx.z;
    const int kvh = h >> 2, tid = threadIdx.x;
    const int qrow0 = b * SEQ + qt * 128;
#if HAVE_TC
    extern __shared__ char smem[];
    const uint32_t sb   = smem_u32(smem);
    const uint32_t base = (sb + 1023u) & ~1023u;
    const uint32_t hdr  = base;
    const uint32_t tile = base + 1024;
    char* tp = smem + (tile - sb);
    const int wid = tid >> 5, lane = tid & 31;

    if (wid == 0) TCGEN05_ALLOC(hdr, 512);
    if (tid == 0) { MBARRIER_INIT(hdr + 16, 1); MBARRIER_INIT(hdr + 24, 1); }
    __syncthreads();
    uint32_t tmem;
    asm volatile("ld.shared.b32 %0, [%1];" : "=r"(tmem) : "r"(hdr));
    const uint32_t Q_T = tmem, S_T = tmem + 128, O_T = tmem + 256;
    const uint32_t PH_T = tmem + 384, PL_T = tmem + 448;

    // ---- Q -> TMEM (rows = 128 threads of warps 0-3) ----
    if (tid < 128) {
        const uint32_t woff = ((uint32_t)wid) << 21;
        uint32_t r[64];
        const uint4* srch = (const uint4*)(qh + (size_t)(qrow0 + tid) * DIM + h * HD);
#pragma unroll
        for (int i = 0; i < 16; i++) ((uint4*)r)[i] = srch[i];
        TCGEN05_ST_X32(Q_T + 0  + woff, r);
        TCGEN05_ST_X32(Q_T + 32 + woff, r + 32);
        const uint4* srcl = (const uint4*)(ql + (size_t)(qrow0 + tid) * DIM + h * HD);
#pragma unroll
        for (int i = 0; i < 16; i++) ((uint4*)r)[i] = srcl[i];
        TCGEN05_ST_X32(Q_T + 64 + woff, r);
        TCGEN05_ST_X32(Q_T + 96 + woff, r + 32);
        TCGEN05_WAIT_ST();
    }

    // ---- prologue: load K(0) into Kbuf0 ----
    {
        const int kvrow0 = b * SEQ;
#pragma unroll 4
        for (int i = 0; i < 16; i++) {
            int s = tid + (i << 8);
            int a = s >> 10, seg = s & 1023, row = seg >> 3, sg = seg & 7;
            const __nv_bfloat16* bsrc = (a >= 2) ? kl : kh;
            *(uint4*)(tp + a * 16384 + swz((uint32_t)(row * 128 + sg * 16))) =
                *(const uint4*)(bsrc + (size_t)(kvrow0 + row) * KVDIM + kvh * HD + (a & 1) * 64 + sg * 8);
        }
    }
    TCGEN05_FENCE_BEFORE();
    FENCE_ASYNC_SHARED();
    __syncthreads();

    float lsum = 0.f;

    for (int kt = 0; kt < SEQ / 128; kt++) {
        const uint32_t koff = (uint32_t)(kt & 1) * 65536u;

        // ---- issue S = Q K^T (TS mode, bf16x3) ----
        if (wid == 0) {
            TCGEN05_FENCE_AFTER();
            if (elect_one()) {
#pragma unroll
                for (int st = 0; st < 8; st++) {
                    uint32_t ahi = Q_T + st * 8, alo = Q_T + 64 + st * 8;
                    uint64_t bhd = make_desc(tile + koff + (st >> 2) * 16384) + (st & 3) * 2;
                    uint64_t bld = make_desc(tile + koff + 32768 + (st >> 2) * 16384) + (st & 3) * 2;
                    mma_f16_ts(S_T, ahi, bhd, GEMM_IDESC, st > 0 ? 1u : 0u);
                    mma_f16_ts(S_T, ahi, bld, GEMM_IDESC, 1u);
                    mma_f16_ts(S_T, alo, bhd, GEMM_IDESC, 1u);
                }
                TCGEN05_COMMIT(hdr + 16);
            }
        }

        // ---- load V(kt) (overlaps S-MMA) ----
        {
            const int vcol0 = kt * 128;
#pragma unroll 4
            for (int i = 0; i < 16; i++) {
                int s = tid + (i << 8);
                int a = s >> 10, seg = s & 1023, row = seg >> 3, sg = seg & 7;
                const __nv_bfloat16* bsrc = (a >= 2) ? vtl : vth;
                *(uint4*)(tp + 131072 + a * 16384 + swz((uint32_t)(row * 128 + sg * 16))) =
                    *(const uint4*)(bsrc + ((size_t)((b * NKV + kvh) * HD + row)) * SEQ
                                    + vcol0 + (a & 1) * 64 + sg * 8);
            }
        }
        FENCE_ASYNC_SHARED();

        // ---- wait S, softmax (no max: |s| <= sqrt(128)), P -> TMEM ----
        MBARRIER_WAIT_PARITY(hdr + 16, (uint32_t)(kt & 1));
        TCGEN05_FENCE_AFTER();
        if (wid < 4) {
            float sum = 0.f;
            const uint32_t woff = ((uint32_t)wid) << 21;
#pragma unroll
            for (int g = 0; g < 4; g++) {
                uint32_t r[32];
                TCGEN05_LD_X32(r, S_T + g * 32);
                TCGEN05_WAIT_LD();
                uint32_t hw[16], lw[16];
#pragma unroll
                for (int j = 0; j < 16; j++) {
                    float p0 = __expf(__uint_as_float(r[2 * j]));
                    float p1 = __expf(__uint_as_float(r[2 * j + 1]));
                    sum += p0 + p1;
                    __nv_bfloat16 h0 = __float2bfloat16(p0);
                    __nv_bfloat16 h1 = __float2bfloat16(p1);
                    __nv_bfloat162 hp(h0, h1);
                    __nv_bfloat162 lp(__float2bfloat16(p0 - __bfloat162float(h0)),
                                      __float2bfloat16(p1 - __bfloat162float(h1)));
                    hw[j] = *(uint32_t*)&hp;
                    lw[j] = *(uint32_t*)&lp;
                }
                TCGEN05_ST_X16(PH_T + g * 16 + woff, hw);
                TCGEN05_ST_X16(PL_T + g * 16 + woff, lw);
            }
            TCGEN05_WAIT_ST();
            lsum += sum;
            TCGEN05_FENCE_BEFORE();
        }
        __syncthreads();   // P + V both visible

        // ---- issue O += P V (TS mode) ----
        if (wid == 0) {
            TCGEN05_FENCE_AFTER();
            if (elect_one()) {
#pragma unroll
                for (int st = 0; st < 8; st++) {
                    uint32_t ahi = PH_T + st * 8, alo = PL_T + st * 8;
                    uint64_t bhd = make_desc(tile + 131072 + (st >> 2) * 16384) + (st & 3) * 2;
                    uint64_t bld = make_desc(tile + 131072 + 32768 + (st >> 2) * 16384) + (st & 3) * 2;
                    uint32_t en0 = (kt == 0 && st == 0) ? 0u : 1u;
                    mma_f16_ts(O_T, ahi, bhd, GEMM_IDESC, en0);
                    mma_f16_ts(O_T, ahi, bld, GEMM_IDESC, 1u);
                    mma_f16_ts(O_T, alo, bhd, GEMM_IDESC, 1u);
                }
                TCGEN05_COMMIT(hdr + 24);
            }
        }

        // ---- prefetch K(kt+1) (overlaps O-MMA) ----
        if (kt < SEQ / 128 - 1) {
            const int kvrow0 = b * SEQ + (kt + 1) * 128;
            const uint32_t koff2 = (uint32_t)((kt + 1) & 1) * 65536u;
#pragma unroll 4
            for (int i = 0; i < 16; i++) {
                int s = tid + (i << 8);
                int a = s >> 10, seg = s & 1023, row = seg >> 3, sg = seg & 7;
                const __nv_bfloat16* bsrc = (a >= 2) ? kl : kh;
                *(uint4*)(tp + koff2 + a * 16384 + swz((uint32_t)(row * 128 + sg * 16))) =
                    *(const uint4*)(bsrc + (size_t)(kvrow0 + row) * KVDIM + kvh * HD + (a & 1) * 64 + sg * 8);
            }
        }
        FENCE_ASYNC_SHARED();
        __syncthreads();   // K(kt+1) ready, all threads past P/V use

        // O(kt) must finish before next iteration overwrites P
        MBARRIER_WAIT_PARITY(hdr + 24, (uint32_t)(kt & 1));
    }

    TCGEN05_FENCE_AFTER();
    if (wid < 4) {
        float inv = 1.f / lsum;
        float* aob = ao + (size_t)(qrow0 + wid * 32 + lane) * DIM + h * HD;
#pragma unroll
        for (int g = 0; g < 4; g++) {
            uint32_t r[32];
            TCGEN05_LD_X32(r, O_T + g * 32);
            TCGEN05_WAIT_LD();
            float* f = (float*)r;
#pragma unroll
            for (int q4 = 0; q4 < 8; q4++)
                *(float4*)(aob + g * 32 + q4 * 4) =
                    make_float4(f[q4*4]*inv, f[q4*4+1]*inv, f[q4*4+2]*inv, f[q4*4+3]*inv);
        }
    }
    __syncthreads();
    if (wid == 0) { TCGEN05_RELINQ(); TCGEN05_DEALLOC(tmem, 512); }
#else
    // naive fallback (never selected)
    if (tid < 128) {
        int grow = qrow0 + tid;
        float l = 0.f;
        for (int d = 0; d < 128; d++) ao[(size_t)grow * DIM + h * HD + d] = 0.f;
        for (int kv = 0; kv < SEQ; kv++) {
            float s = 0.f;
            size_t ko = (size_t)(b * SEQ + kv) * KVDIM + kvh * HD;
            size_t qo = (size_t)grow * DIM + h * HD;
            for (int d = 0; d < 128; d++)
                s += (__bfloat162float(qh[qo+d]) + __bfloat162float(ql[qo+d])) *
                     (__bfloat162float(kh[ko+d]) + __bfloat162float(kl[ko+d]));
            float p = __expf(s);
            l += p;
            for (int d = 0; d < 128; d++) {
                size_t vo = ((size_t)((b * NKV + kvh) * HD + d)) * SEQ + kv;
                ao[(size_t)grow * DIM + h * HD + d] +=
                    p * (__bfloat162float(vth[vo]) + __bfloat162float(vtl[vo]));
            }
        }
        for (int d = 0; d < 128; d++) ao[(size_t)grow * DIM + h * HD + d] /= l;
    }
#endif
}

// -----------------------------------------------------------------------------
extern "C" void kernel_launch(void* const* d_in, const int* in_sizes, int n_in,
                              void* d_out, int out_size) {
    const float* x   = (const float*)d_in[0];
    const float* Wq  = (const float*)d_in[1];
    const float* Wk  = (const float*)d_in[2];
    const float* Wv  = (const float*)d_in[3];
    const float* Wo  = (const float*)d_in[4];
    const float* qnw = (const float*)d_in[5];
    const float* knw = (const float*)d_in[6];
    float* out = (float*)d_out;

    float *q, *k, *v, *ao;
    cudaGetSymbolAddress((void**)&q,  g_q);
    cudaGetSymbolAddress((void**)&k,  g_k);
    cudaGetSymbolAddress((void**)&v,  g_v);
    cudaGetSymbolAddress((void**)&ao, g_ao);
    __nv_bfloat16 *xh,*xl,*aoh,*aol,*wqh,*wql,*wkh,*wkl,*wvh,*wvl,*woh,*wol;
    __nv_bfloat16 *qbh,*qbl,*kbh,*kbl,*vth,*vtl;
    cudaGetSymbolAddress((void**)&xh,  g_xh);  cudaGetSymbolAddress((void**)&xl,  g_xl);
    cudaGetSymbolAddress((void**)&aoh, g_aoh); cudaGetSymbolAddress((void**)&aol, g_aol);
    cudaGetSymbolAddress((void**)&wqh, g_wqh); cudaGetSymbolAddress((void**)&wql, g_wql);
    cudaGetSymbolAddress((void**)&wkh, g_wkh); cudaGetSymbolAddress((void**)&wkl, g_wkl);
    cudaGetSymbolAddress((void**)&wvh, g_wvh); cudaGetSymbolAddress((void**)&wvl, g_wvl);
    cudaGetSymbolAddress((void**)&woh, g_woh); cudaGetSymbolAddress((void**)&wol, g_wol);
    cudaGetSymbolAddress((void**)&qbh, g_qbh); cudaGetSymbolAddress((void**)&qbl, g_qbl);
    cudaGetSymbolAddress((void**)&kbh, g_kbh); cudaGetSymbolAddress((void**)&kbl, g_kbl);
    cudaGetSymbolAddress((void**)&vth, g_vth); cudaGetSymbolAddress((void**)&vtl, g_vtl);

    cudaFuncSetAttribute(gemm_qkv, cudaFuncAttributeMaxDynamicSharedMemorySize, GEMM_SMEM);
    cudaFuncSetAttribute(gemm_pre, cudaFuncAttributeMaxDynamicSharedMemorySize, GEMM_SMEM);
    cudaFuncSetAttribute(flash_tc, cudaFuncAttributeMaxDynamicSharedMemorySize, FL_SMEM);

    // user launch #1: weight transposes + x conversion
    prep<<<dim3(64, 64, 5), 256>>>(Wq, Wk, Wv, Wo, x,
                                   wqh, wql, wkh, wkl, wvh, wvl, woh, wol, xh, xl);
    // #2: Q/K/V projections
    gemm_qkv<<<dim3(16, 32, 3), 256, GEMM_SMEM>>>(xh, xl, wqh, wql, wkh, wkl,
                                                  wvh, wvl, q, k, v);
    // #3: norm + rope + V transpose
    normropev<<<dim3(MROWS, NH + NKV + 4), 128>>>(q, k, v, qnw, knw,
                                                  qbh, qbl, kbh, kbl, vth, vtl);
    // #4: flash attention  (ncu-captured position)
    flash_tc<<<dim3(SEQ / 128, NH, BATCH), 256, FL_SMEM>>>(qbh, qbl, kbh, kbl, vth, vtl, ao);
    // #5: convert attention output
    cvt32<<<(MROWS * DIM / 4 + 255) / 256, 256>>>(ao, aoh, aol, MROWS * DIM / 4);
    // #6: output projection
    gemm_pre<<<dim3(16, 32), 256, GEMM_SMEM>>>(aoh, aol, woh, wol, out, DIM, DIM);
}

// round 7
// speedup vs baseline: 5.6905x; 3.4612x over previous
#include <cuda_runtime.h>
#include <cuda_bf16.h>
#include <math.h>
#include <stdint.h>

#define BATCH 2
#define SEQ   2048
#define DIM   2048
#define NH    16
#define NKV   4
#define HD    128
#define MROWS (BATCH*SEQ)
#define KVDIM (NKV*HD)

#if defined(__CUDA_ARCH__) && defined(__CUDA_ARCH_FEAT_SM103_ALL)
#define HAVE_TC 1
#else
#define HAVE_TC 0
#endif

// ---------------- scratch ---------------------------------------------------
__device__ float g_q [MROWS*DIM];
__device__ float g_k [MROWS*KVDIM];
__device__ float g_v [MROWS*KVDIM];
__device__ float g_ct[SEQ*64], g_st[SEQ*64];          // RoPE tables
__device__ __nv_bfloat16 g_xh [MROWS*DIM],   g_xl [MROWS*DIM];
__device__ __nv_bfloat16 g_aoh[MROWS*DIM],   g_aol[MROWS*DIM];
__device__ __nv_bfloat16 g_wqh[DIM*DIM],     g_wql[DIM*DIM];
__device__ __nv_bfloat16 g_wkh[KVDIM*DIM],   g_wkl[KVDIM*DIM];
__device__ __nv_bfloat16 g_wvh[KVDIM*DIM],   g_wvl[KVDIM*DIM];
__device__ __nv_bfloat16 g_woh[DIM*DIM],     g_wol[DIM*DIM];
__device__ __nv_bfloat16 g_qbh[MROWS*DIM],   g_qbl[MROWS*DIM];
__device__ __nv_bfloat16 g_kbh[MROWS*KVDIM], g_kbl[MROWS*KVDIM];
__device__ __nv_bfloat16 g_vth[MROWS*KVDIM], g_vtl[MROWS*KVDIM]; // V^T [b][kv][d][s]

__device__ __forceinline__ uint32_t swz(uint32_t off) {
    return off ^ ((off >> 3) & 0x70u);
}

#if HAVE_TC
__device__ __forceinline__ uint32_t smem_u32(const void* p) {
    uint32_t a;
    asm("{ .reg .u64 t; cvta.to.shared.u64 t, %1; cvt.u32.u64 %0, t; }" : "=r"(a) : "l"(p));
    return a;
}
__device__ __forceinline__ uint32_t elect_one() {
    uint32_t pred;
    asm volatile("{ .reg .pred p; elect.sync _|p, 0xFFFFFFFF; selp.b32 %0,1,0,p; }" : "=r"(pred));
    return pred;
}
#define MBARRIER_INIT(addr, cnt) \
    asm volatile("mbarrier.init.shared.b64 [%0], %1;" :: "r"(addr), "r"(cnt) : "memory")
#define MBARRIER_WAIT_PARITY(addr, par) do {                                   \
    uint32_t _m = (addr), _p = (par), _d;                                      \
    asm volatile("{ .reg .pred p; mbarrier.try_wait.parity.acquire.cta.shared::cta.b64 p, [%1], %2; selp.b32 %0,1,0,p; }" \
                 : "=r"(_d) : "r"(_m), "r"(_p) : "memory");                    \
    if (!_d) {                                                                 \
        asm volatile("{ .reg .pred P1; WL_%=: mbarrier.try_wait.parity.acquire.cta.shared::cta.b64 P1, [%0], %1, 0x989680; @P1 bra.uni WD_%=; bra.uni WL_%=; WD_%=: }" \
                     :: "r"(_m), "r"(_p) : "memory");                          \
    }                                                                          \
} while (0)
#define TCGEN05_ALLOC(res, n) \
    asm volatile("tcgen05.alloc.cta_group::1.sync.aligned.shared::cta.b32 [%0], %1;" :: "r"(res), "r"(n) : "memory")
#define TCGEN05_DEALLOC(t, n) \
    asm volatile("tcgen05.dealloc.cta_group::1.sync.aligned.b32 %0, %1;" :: "r"(t), "r"(n))
#define TCGEN05_RELINQ() \
    asm volatile("tcgen05.relinquish_alloc_permit.cta_group::1.sync.aligned;")
#define TCGEN05_COMMIT(mb) \
    asm volatile("tcgen05.commit.cta_group::1.mbarrier::arrive::one.shared::cluster.b64 [%0];" :: "r"(mb) : "memory")
#define TCGEN05_FENCE_BEFORE() asm volatile("tcgen05.fence::before_thread_sync;" ::: "memory")
#define TCGEN05_FENCE_AFTER()  asm volatile("tcgen05.fence::after_thread_sync;" ::: "memory")
#define TCGEN05_WAIT_LD()      asm volatile("tcgen05.wait::ld.sync.aligned;" ::: "memory")
#define TCGEN05_WAIT_ST()      asm volatile("tcgen05.wait::st.sync.aligned;" ::: "memory")
#define FENCE_ASYNC_SHARED()   asm volatile("fence.proxy.async.shared::cta;" ::: "memory")
#define TCGEN05_LD_X32(r, a)                                                   \
    asm volatile("tcgen05.ld.sync.aligned.32x32b.x32.b32 "                     \
        "{%0,%1,%2,%3,%4,%5,%6,%7,%8,%9,%10,%11,%12,%13,%14,%15,"              \
        "%16,%17,%18,%19,%20,%21,%22,%23,%24,%25,%26,%27,%28,%29,%30,%31}, [%32];" \
        : "=r"((r)[0]),"=r"((r)[1]),"=r"((r)[2]),"=r"((r)[3]),                 \
          "=r"((r)[4]),"=r"((r)[5]),"=r"((r)[6]),"=r"((r)[7]),                 \
          "=r"((r)[8]),"=r"((r)[9]),"=r"((r)[10]),"=r"((r)[11]),               \
          "=r"((r)[12]),"=r"((r)[13]),"=r"((r)[14]),"=r"((r)[15]),             \
          "=r"((r)[16]),"=r"((r)[17]),"=r"((r)[18]),"=r"((r)[19]),             \
          "=r"((r)[20]),"=r"((r)[21]),"=r"((r)[22]),"=r"((r)[23]),             \
          "=r"((r)[24]),"=r"((r)[25]),"=r"((r)[26]),"=r"((r)[27]),             \
          "=r"((r)[28]),"=r"((r)[29]),"=r"((r)[30]),"=r"((r)[31])              \
        : "r"(a))
#define TCGEN05_ST_X16(a, r)                                                   \
    asm volatile("tcgen05.st.sync.aligned.32x32b.x16.b32 [%0], "               \
        "{%1,%2,%3,%4,%5,%6,%7,%8,%9,%10,%11,%12,%13,%14,%15,%16};"            \
        :: "r"(a),                                                             \
           "r"((r)[0]),"r"((r)[1]),"r"((r)[2]),"r"((r)[3]),                    \
           "r"((r)[4]),"r"((r)[5]),"r"((r)[6]),"r"((r)[7]),                    \
           "r"((r)[8]),"r"((r)[9]),"r"((r)[10]),"r"((r)[11]),                  \
           "r"((r)[12]),"r"((r)[13]),"r"((r)[14]),"r"((r)[15])                 \
        : "memory")
#define TCGEN05_ST_X32(a, r)                                                   \
    asm volatile("tcgen05.st.sync.aligned.32x32b.x32.b32 [%0], "               \
        "{%1,%2,%3,%4,%5,%6,%7,%8,%9,%10,%11,%12,%13,%14,%15,%16,"             \
        "%17,%18,%19,%20,%21,%22,%23,%24,%25,%26,%27,%28,%29,%30,%31,%32};"    \
        :: "r"(a),                                                             \
           "r"((r)[0]),"r"((r)[1]),"r"((r)[2]),"r"((r)[3]),                    \
           "r"((r)[4]),"r"((r)[5]),"r"((r)[6]),"r"((r)[7]),                    \
           "r"((r)[8]),"r"((r)[9]),"r"((r)[10]),"r"((r)[11]),                  \
           "r"((r)[12]),"r"((r)[13]),"r"((r)[14]),"r"((r)[15]),                \
           "r"((r)[16]),"r"((r)[17]),"r"((r)[18]),"r"((r)[19]),                \
           "r"((r)[20]),"r"((r)[21]),"r"((r)[22]),"r"((r)[23]),                \
           "r"((r)[24]),"r"((r)[25]),"r"((r)[26]),"r"((r)[27]),                \
           "r"((r)[28]),"r"((r)[29]),"r"((r)[30]),"r"((r)[31])                 \
        : "memory")

__device__ __forceinline__ uint64_t make_desc(uint32_t addr) {
    return ((uint64_t)2u << 61) | ((uint64_t)1u << 46)
         | ((uint64_t)64u << 32) | ((uint64_t)1u << 16)
         | ((uint64_t)(addr >> 4) & 0x3FFFu);
}
__device__ __forceinline__ void mma_f16_ss(uint32_t d, uint64_t a, uint64_t b,
                                           uint32_t idesc, uint32_t en) {
    asm volatile("{ .reg .pred p; setp.ne.u32 p, %5, 0;\n\t"
        "tcgen05.mma.cta_group::1.kind::f16 [%0], %1, %2, %3, {%4,%4,%4,%4}, p; }"
        :: "r"(d), "l"(a), "l"(b), "r"(idesc), "r"(0u), "r"(en) : "memory");
}
__device__ __forceinline__ void mma_f16_ts(uint32_t d, uint32_t a, uint64_t b,
                                           uint32_t idesc, uint32_t en) {
    asm volatile("{ .reg .pred p; setp.ne.u32 p, %5, 0;\n\t"
        "tcgen05.mma.cta_group::1.kind::f16 [%0], [%1], %2, %3, {%4,%4,%4,%4}, p; }"
        :: "r"(d), "r"(a), "l"(b), "r"(idesc), "r"(0u), "r"(en) : "memory");
}
#define GEMM_IDESC (0x490u | (16u << 17) | (8u << 24))  // F32 acc, bf16, M=128, N=128
#endif // HAVE_TC

// ---------------- RoPE tables (one-time, double precision) ------------------
__global__ __launch_bounds__(128) void rope_tab(float* __restrict__ ct,
                                                float* __restrict__ st) {
    int i = blockIdx.x * 128 + threadIdx.x;      // SEQ*64
    int s = i >> 6, j = i & 63;
    float invf  = (float)exp(-9.210340371976184 * ((double)(2 * j) * (1.0 / 128.0)));
    float theta = (float)s * invf;
    double td = (double)theta;
    ct[i] = (float)cos(td);
    st[i] = (float)sin(td);
}

// ---------------- weight transposes (z-sliced over 4 weights) ---------------
__global__ __launch_bounds__(256) void prep_w(const float* __restrict__ Wq,
                                              const float* __restrict__ Wk,
                                              const float* __restrict__ Wv,
                                              const float* __restrict__ Wo,
                                              __nv_bfloat16* __restrict__ wqh, __nv_bfloat16* __restrict__ wql,
                                              __nv_bfloat16* __restrict__ wkh, __nv_bfloat16* __restrict__ wkl,
                                              __nv_bfloat16* __restrict__ wvh, __nv_bfloat16* __restrict__ wvl,
                                              __nv_bfloat16* __restrict__ woh, __nv_bfloat16* __restrict__ wol) {
    const int z = blockIdx.z;
    const float* W;
    __nv_bfloat16 *th, *tl;
    int N;
    if      (z == 0) { W = Wq; th = wqh; tl = wql; N = DIM;   }
    else if (z == 1) { W = Wk; th = wkh; tl = wkl; N = KVDIM; }
    else if (z == 2) { W = Wv; th = wvh; tl = wvl; N = KVDIM; }
    else             { W = Wo; th = woh; tl = wol; N = DIM;   }
    const int n0 = blockIdx.x * 32, k0 = blockIdx.y * 32;
    if (n0 >= N) return;
    __shared__ float smt[32][33];
    const int tx = threadIdx.x & 31, ty = threadIdx.x >> 5;
#pragma unroll
    for (int i = 0; i < 4; i++)
        smt[ty + 8 * i][tx] = W[(size_t)(k0 + ty + 8 * i) * N + n0 + tx];
    __syncthreads();
#pragma unroll
    for (int i = 0; i < 4; i++) {
        int nl = ty + 8 * i;
        float f = smt[tx][nl];
        __nv_bfloat16 h = __float2bfloat16(f);
        th[(size_t)(n0 + nl) * DIM + k0 + tx] = h;
        tl[(size_t)(n0 + nl) * DIM + k0 + tx] = __float2bfloat16(f - __bfloat162float(h));
    }
}

// ---------------- x conversion ----------------------------------------------
__global__ __launch_bounds__(256) void prep_x(const float* __restrict__ x,
                                              __nv_bfloat16* __restrict__ xh,
                                              __nv_bfloat16* __restrict__ xl) {
    int base = blockIdx.x * 256 + threadIdx.x;
#pragma unroll
    for (int rep = 0; rep < 2; rep++) {
        int i = base + rep * 1048576;
        float4 v = *(const float4*)(x + (size_t)i * 4);
        __nv_bfloat16 h0 = __float2bfloat16(v.x), h1 = __float2bfloat16(v.y);
        __nv_bfloat16 h2 = __float2bfloat16(v.z), h3 = __float2bfloat16(v.w);
        __nv_bfloat162 hA(h0, h1), hB(h2, h3);
        __nv_bfloat162 lA(__float2bfloat16(v.x - __bfloat162float(h0)),
                          __float2bfloat16(v.y - __bfloat162float(h1)));
        __nv_bfloat162 lB(__float2bfloat16(v.z - __bfloat162float(h2)),
                          __float2bfloat16(v.w - __bfloat162float(h3)));
        *(uint2*)(xh + (size_t)i * 4) = make_uint2(*(uint32_t*)&hA, *(uint32_t*)&hB);
        *(uint2*)(xl + (size_t)i * 4) = make_uint2(*(uint32_t*)&lA, *(uint32_t*)&lB);
    }
}

// ---------------- GEMM core (bf16x3, preconverted, 512 threads) -------------
#define GEMM_SMEM (1024 + 2*65536)
#if HAVE_TC
__device__ __forceinline__ void gemm_body(const __nv_bfloat16* ah, const __nv_bfloat16* al,
                                          const __nv_bfloat16* bh, const __nv_bfloat16* bl,
                                          float* C, int N, int K, int m0, int n0,
                                          char* smem) {
    const uint32_t sb   = smem_u32(smem);
    const uint32_t base = (sb + 1023u) & ~1023u;
    const uint32_t hdr  = base;
    const uint32_t tile = base + 1024;
    char* tp = smem + (tile - sb);
    const int tid = threadIdx.x, wid = tid >> 5, lane = tid & 31;

    if (wid == 0) TCGEN05_ALLOC(hdr, 128);
    if (tid == 0) { MBARRIER_INIT(hdr + 16, 1); MBARRIER_INIT(hdr + 24, 1); }
    __syncthreads();
    uint32_t tmem;
    asm volatile("ld.shared.b32 %0, [%1];" : "=r"(tmem) : "r"(hdr));

    const int NC = K >> 6;
    for (int c = 0; c < NC; c++) {
        const int buf = c & 1, boff = buf * 65536, k0 = c << 6;
        if (c >= 2)
            MBARRIER_WAIT_PARITY(hdr + 16 + 8 * buf, (uint32_t)(((c >> 1) - 1) & 1));
#pragma unroll
        for (int i = 0; i < 8; i++) {
            int s = tid + (i << 9);
            int a = s >> 10, seg = s & 1023, row = seg >> 3, sg = seg & 7;
            const __nv_bfloat16* src;
            if (a == 0)      src = ah + (size_t)(m0 + row) * K + k0 + sg * 8;
            else if (a == 1) src = al + (size_t)(m0 + row) * K + k0 + sg * 8;
            else if (a == 2) src = bh + (size_t)(n0 + row) * K + k0 + sg * 8;
            else             src = bl + (size_t)(n0 + row) * K + k0 + sg * 8;
            *(uint4*)(tp + boff + a * 16384 + swz((uint32_t)(row * 128 + sg * 16))) =
                *(const uint4*)src;
        }
        FENCE_ASYNC_SHARED();
        __syncthreads();
        if (wid == 0 && elect_one()) {
            uint64_t dah = make_desc(tile + boff);
            uint64_t dal = make_desc(tile + boff + 16384);
            uint64_t dbh = make_desc(tile + boff + 32768);
            uint64_t dbl = make_desc(tile + boff + 49152);
#pragma unroll
            for (int s = 0; s < 4; s++) {
                uint32_t en0 = (c == 0 && s == 0) ? 0u : 1u;
                mma_f16_ss(tmem, dah + s * 2, dbh + s * 2, GEMM_IDESC, en0);
                mma_f16_ss(tmem, dah + s * 2, dbl + s * 2, GEMM_IDESC, 1u);
                mma_f16_ss(tmem, dal + s * 2, dbh + s * 2, GEMM_IDESC, 1u);
            }
            TCGEN05_COMMIT(hdr + 16 + 8 * buf);
        }
    }
    MBARRIER_WAIT_PARITY(hdr + 16 + 8 * ((NC - 1) & 1), (uint32_t)(((NC - 1) >> 1) & 1));
    TCGEN05_FENCE_AFTER();
    if (wid < 4) {
        float* crow = C + (size_t)(m0 + wid * 32 + lane) * N + n0;
#pragma unroll
        for (int g = 0; g < 4; g++) {
            uint32_t r[32];
            TCGEN05_LD_X32(r, tmem + g * 32);
            TCGEN05_WAIT_LD();
            float* f = (float*)r;
#pragma unroll
            for (int q4 = 0; q4 < 8; q4++)
                *(float4*)(crow + g * 32 + q4 * 4) =
                    make_float4(f[q4*4], f[q4*4+1], f[q4*4+2], f[q4*4+3]);
        }
    }
    __syncthreads();
    if (wid == 0) { TCGEN05_RELINQ(); TCGEN05_DEALLOC(tmem, 128); }
}
#endif

// Q/K/V projections: grid (24, 32), 512 thr.  bx<16: Q, 16-19: K, 20-23: V.
__global__ __launch_bounds__(512) void gemm_qkv(const __nv_bfloat16* __restrict__ ah,
                                                const __nv_bfloat16* __restrict__ al,
                                                const __nv_bfloat16* __restrict__ bhq,
                                                const __nv_bfloat16* __restrict__ blq,
                                                const __nv_bfloat16* __restrict__ bhk,
                                                const __nv_bfloat16* __restrict__ blk_,
                                                const __nv_bfloat16* __restrict__ bhv,
                                                const __nv_bfloat16* __restrict__ blv,
                                                float* __restrict__ cq,
                                                float* __restrict__ ck,
                                                float* __restrict__ cv) {
    const int bx = blockIdx.x;
    const __nv_bfloat16 *bh, *bl;
    float* C;
    int N, nb;
    if      (bx < 16) { bh = bhq; bl = blq;  C = cq; N = DIM;   nb = bx;      }
    else if (bx < 20) { bh = bhk; bl = blk_; C = ck; N = KVDIM; nb = bx - 16; }
    else              { bh = bhv; bl = blv;  C = cv; N = KVDIM; nb = bx - 20; }
#if HAVE_TC
    extern __shared__ char smem[];
    gemm_body(ah, al, bh, bl, C, N, DIM, blockIdx.y * 128, nb * 128, smem);
#else
    const int tid = threadIdx.x;
    const int m0 = blockIdx.y * 128, n0 = nb * 128;
    for (int e = tid; e < 128 * 128; e += 512) {
        int i = e >> 7, j = e & 127;
        float acc = 0.f;
        for (int kk = 0; kk < DIM; kk++)
            acc += (__bfloat162float(ah[(size_t)(m0+i)*DIM+kk]) + __bfloat162float(al[(size_t)(m0+i)*DIM+kk])) *
                   (__bfloat162float(bh[(size_t)(n0+j)*DIM+kk]) + __bfloat162float(bl[(size_t)(n0+j)*DIM+kk]));
        C[(size_t)(m0 + i) * N + n0 + j] = acc;
    }
#endif
}

// single GEMM (output projection)
__global__ __launch_bounds__(512) void gemm_pre(const __nv_bfloat16* __restrict__ ah,
                                                const __nv_bfloat16* __restrict__ al,
                                                const __nv_bfloat16* __restrict__ bh,
                                                const __nv_bfloat16* __restrict__ bl,
                                                float* __restrict__ C, int N, int K) {
#if HAVE_TC
    extern __shared__ char smem[];
    gemm_body(ah, al, bh, bl, C, N, K, blockIdx.y * 128, blockIdx.x * 128, smem);
#else
    const int tid = threadIdx.x;
    const int m0 = blockIdx.y * 128, n0 = blockIdx.x * 128;
    for (int e = tid; e < 128 * 128; e += 512) {
        int i = e >> 7, j = e & 127;
        float acc = 0.f;
        for (int kk = 0; kk < K; kk++)
            acc += (__bfloat162float(ah[(size_t)(m0+i)*K+kk]) + __bfloat162float(al[(size_t)(m0+i)*K+kk])) *
                   (__bfloat162float(bh[(size_t)(n0+j)*K+kk]) + __bfloat162float(bl[(size_t)(n0+j)*K+kk]));
        C[(size_t)(m0 + i) * N + n0 + j] = acc;
    }
#endif
}

// ---------------- normrope (table-driven) + V transpose ----------------------
// grid (MROWS, 24), 128 thr.  hy<16: q head; 16..19: k head; 20..23: vconv.
__global__ __launch_bounds__(128) void normropev(const float* __restrict__ q,
                                                 const float* __restrict__ k,
                                                 const float* __restrict__ v,
                                                 const float* __restrict__ qw,
                                                 const float* __restrict__ kw,
                                                 const float* __restrict__ ct,
                                                 const float* __restrict__ st,
                                                 __nv_bfloat16* __restrict__ qbh,
                                                 __nv_bfloat16* __restrict__ qbl,
                                                 __nv_bfloat16* __restrict__ kbh,
                                                 __nv_bfloat16* __restrict__ kbl,
                                                 __nv_bfloat16* __restrict__ vh,
                                                 __nv_bfloat16* __restrict__ vl) {
    const int row = blockIdx.x, hy = blockIdx.y, d = threadIdx.x;

    if (hy >= NH + NKV) {
        int vb = (hy - (NH + NKV)) * MROWS + row;
        int o = vb * 128 + d;
        int s = o & (SEQ - 1);
        int rest = o >> 11;
        int dd = rest & (HD - 1);
        int bkv = rest >> 7;
        int b = bkv >> 2, kv = bkv & 3;
        float f = v[(size_t)(b * SEQ + s) * KVDIM + kv * HD + dd];
        __nv_bfloat16 h = __float2bfloat16(f);
        vh[o] = h;
        vl[o] = __float2bfloat16(f - __bfloat162float(h));
        return;
    }

    const int s = row & (SEQ - 1);
    const float* p;
    const float* w;
    if (hy < NH) { p = q + (size_t)row * DIM   + hy * HD;        w = qw; }
    else         { p = k + (size_t)row * KVDIM + (hy - NH) * HD; w = kw; }

    float x = p[d];
    float v2 = x * x;
#pragma unroll
    for (int off = 16; off > 0; off >>= 1)
        v2 += __shfl_xor_sync(0xffffffffu, v2, off);
    __shared__ float wsum[4];
    const int lane = d & 31, wrp = d >> 5;
    if (lane == 0) wsum[wrp] = v2;
    __syncthreads();
    float total = wsum[0] + wsum[1] + wsum[2] + wsum[3];
    float rn = rsqrtf(total * (1.0f / 128.0f) + 1e-6f);
    float nx = x * rn * w[d];
    __shared__ float sn[128];
    sn[d] = nx;
    __syncthreads();

    const int j = d & 63;
    float c  = ct[s * 64 + j];
    float si = st[s * 64 + j];
    float out = (d < 64) ? (nx * c - sn[d + 64] * si)
                         : (nx * c + sn[d - 64] * si);
    if (hy < NH) {
        float o2 = out * 0.08838834764831843f;
        __nv_bfloat16 hh = __float2bfloat16(o2);
        size_t o = (size_t)row * DIM + hy * HD + d;
        qbh[o] = hh;
        qbl[o] = __float2bfloat16(o2 - __bfloat162float(hh));
    } else {
        __nv_bfloat16 hh = __float2bfloat16(out);
        size_t o = (size_t)row * KVDIM + (hy - NH) * HD + d;
        kbh[o] = hh;
        kbl[o] = __float2bfloat16(out - __bfloat162float(hh));
    }
}

// ---------------- flash attention, pipelined tcgen05, 8-warp softmax --------
// grid (SEQ/128, NH, BATCH), 256 thr.
// smem: hdr 1024 | sums 1024 | Kbuf0 64KB | Kbuf1 64KB | Vbuf 64KB
// TMEM: Q@0(128: hi 0-63, lo 64-127), S@128, O@256, PH@384, PL@448
#define FL_SMEM (1024 + 2048 + 3*65536)
__global__ __launch_bounds__(256) void flash_tc(const __nv_bfloat16* __restrict__ qh,
                                                const __nv_bfloat16* __restrict__ ql,
                                                const __nv_bfloat16* __restrict__ kh,
                                                const __nv_bfloat16* __restrict__ kl,
                                                const __nv_bfloat16* __restrict__ vth,
                                                const __nv_bfloat16* __restrict__ vtl,
                                                __nv_bfloat16* __restrict__ aoh,
                                                __nv_bfloat16* __restrict__ aol) {
    const int qt = blockIdx.x, h = blockIdx.y, b = blockIdx.z;
    const int kvh = h >> 2, tid = threadIdx.x;
    const int qrow0 = b * SEQ + qt * 128;
#if HAVE_TC
    extern __shared__ char smem[];
    const uint32_t sb   = smem_u32(smem);
    const uint32_t base = (sb + 1023u) & ~1023u;
    const uint32_t hdr  = base;
    const uint32_t tile = base + 2048;
    char* tp = smem + (tile - sb);
    float* sums = (float*)(smem + (base + 1024 - sb));   // [2][128]
    const int wid = tid >> 5, lane = tid & 31;
    const int sp = wid & 3, half = wid >> 2;

    if (wid == 0) TCGEN05_ALLOC(hdr, 512);
    if (tid == 0) { MBARRIER_INIT(hdr + 16, 1); MBARRIER_INIT(hdr + 24, 1); }
    __syncthreads();
    uint32_t tmem;
    asm volatile("ld.shared.b32 %0, [%1];" : "=r"(tmem) : "r"(hdr));
    const uint32_t Q_T = tmem, S_T = tmem + 128, O_T = tmem + 256;
    const uint32_t PH_T = tmem + 384, PL_T = tmem + 448;

    // ---- Q -> TMEM ----
    if (tid < 128) {
        const uint32_t woff = ((uint32_t)wid) << 21;
        uint32_t r[64];
        const uint4* srch = (const uint4*)(qh + (size_t)(qrow0 + tid) * DIM + h * HD);
#pragma unroll
        for (int i = 0; i < 16; i++) ((uint4*)r)[i] = srch[i];
        TCGEN05_ST_X32(Q_T + 0  + woff, r);
        TCGEN05_ST_X32(Q_T + 32 + woff, r + 32);
        const uint4* srcl = (const uint4*)(ql + (size_t)(qrow0 + tid) * DIM + h * HD);
#pragma unroll
        for (int i = 0; i < 16; i++) ((uint4*)r)[i] = srcl[i];
        TCGEN05_ST_X32(Q_T + 64 + woff, r);
        TCGEN05_ST_X32(Q_T + 96 + woff, r + 32);
        TCGEN05_WAIT_ST();
    }

    // ---- prologue: K(0) -> Kbuf0 ----
    {
        const int kvrow0 = b * SEQ;
#pragma unroll 4
        for (int i = 0; i < 16; i++) {
            int s = tid + (i << 8);
            int a = s >> 10, seg = s & 1023, row = seg >> 3, sg = seg & 7;
            const __nv_bfloat16* bsrc = (a >= 2) ? kl : kh;
            *(uint4*)(tp + a * 16384 + swz((uint32_t)(row * 128 + sg * 16))) =
                *(const uint4*)(bsrc + (size_t)(kvrow0 + row) * KVDIM + kvh * HD + (a & 1) * 64 + sg * 8);
        }
    }
    TCGEN05_FENCE_BEFORE();
    FENCE_ASYNC_SHARED();
    __syncthreads();

    float psum = 0.f;

    for (int kt = 0; kt < SEQ / 128; kt++) {
        const uint32_t koff = (uint32_t)(kt & 1) * 65536u;

        // ---- issue S = Q K^T ----
        if (wid == 0) {
            TCGEN05_FENCE_AFTER();
            if (elect_one()) {
#pragma unroll
                for (int st = 0; st < 8; st++) {
                    uint32_t ahi = Q_T + st * 8, alo = Q_T + 64 + st * 8;
                    uint64_t bhd = make_desc(tile + koff + (st >> 2) * 16384) + (st & 3) * 2;
                    uint64_t bld = make_desc(tile + koff + 32768 + (st >> 2) * 16384) + (st & 3) * 2;
                    mma_f16_ts(S_T, ahi, bhd, GEMM_IDESC, st > 0 ? 1u : 0u);
                    mma_f16_ts(S_T, ahi, bld, GEMM_IDESC, 1u);
                    mma_f16_ts(S_T, alo, bhd, GEMM_IDESC, 1u);
                }
                TCGEN05_COMMIT(hdr + 16);
            }
        }

        // ---- load V(kt) (overlaps S-MMA) ----
        {
            const int vcol0 = kt * 128;
#pragma unroll 4
            for (int i = 0; i < 16; i++) {
                int s = tid + (i << 8);
                int a = s >> 10, seg = s & 1023, row = seg >> 3, sg = seg & 7;
                const __nv_bfloat16* bsrc = (a >= 2) ? vtl : vth;
                *(uint4*)(tp + 131072 + a * 16384 + swz((uint32_t)(row * 128 + sg * 16))) =
                    *(const uint4*)(bsrc + ((size_t)((b * NKV + kvh) * HD + row)) * SEQ
                                    + vcol0 + (a & 1) * 64 + sg * 8);
            }
        }
        FENCE_ASYNC_SHARED();

        // ---- wait S, 8-warp softmax, P -> TMEM ----
        MBARRIER_WAIT_PARITY(hdr + 16, (uint32_t)(kt & 1));
        TCGEN05_FENCE_AFTER();
        {
            float sum = 0.f;
            const uint32_t woff = ((uint32_t)sp) << 21;
#pragma unroll
            for (int gg = 0; gg < 2; gg++) {
                int g = half * 2 + gg;
                uint32_t r[32];
                TCGEN05_LD_X32(r, S_T + g * 32);
                TCGEN05_WAIT_LD();
                uint32_t hw[16], lw[16];
#pragma unroll
                for (int j = 0; j < 16; j++) {
                    float p0 = __expf(__uint_as_float(r[2 * j]));
                    float p1 = __expf(__uint_as_float(r[2 * j + 1]));
                    sum += p0 + p1;
                    __nv_bfloat16 h0 = __float2bfloat16(p0);
                    __nv_bfloat16 h1 = __float2bfloat16(p1);
                    __nv_bfloat162 hp(h0, h1);
                    __nv_bfloat162 lp(__float2bfloat16(p0 - __bfloat162float(h0)),
                                      __float2bfloat16(p1 - __bfloat162float(h1)));
                    hw[j] = *(uint32_t*)&hp;
                    lw[j] = *(uint32_t*)&lp;
                }
                TCGEN05_ST_X16(PH_T + g * 16 + woff, hw);
                TCGEN05_ST_X16(PL_T + g * 16 + woff, lw);
            }
            TCGEN05_WAIT_ST();
            psum += sum;
            TCGEN05_FENCE_BEFORE();
        }
        __syncthreads();   // P + V both ready

        // ---- issue O += P V ----
        if (wid == 0) {
            TCGEN05_FENCE_AFTER();
            if (elect_one()) {
#pragma unroll
                for (int st = 0; st < 8; st++) {
                    uint32_t ahi = PH_T + st * 8, alo = PL_T + st * 8;
                    uint64_t bhd = make_desc(tile + 131072 + (st >> 2) * 16384) + (st & 3) * 2;
                    uint64_t bld = make_desc(tile + 131072 + 32768 + (st >> 2) * 16384) + (st & 3) * 2;
                    uint32_t en0 = (kt == 0 && st == 0) ? 0u : 1u;
                    mma_f16_ts(O_T, ahi, bhd, GEMM_IDESC, en0);
                    mma_f16_ts(O_T, ahi, bld, GEMM_IDESC, 1u);
                    mma_f16_ts(O_T, alo, bhd, GEMM_IDESC, 1u);
                }
                TCGEN05_COMMIT(hdr + 24);
            }
        }

        // ---- prefetch K(kt+1) (overlaps O-MMA) ----
        if (kt < SEQ / 128 - 1) {
            const int kvrow0 = b * SEQ + (kt + 1) * 128;
            const uint32_t koff2 = (uint32_t)((kt + 1) & 1) * 65536u;
#pragma unroll 4
            for (int i = 0; i < 16; i++) {
                int s = tid + (i << 8);
                int a = s >> 10, seg = s & 1023, row = seg >> 3, sg = seg & 7;
                const __nv_bfloat16* bsrc = (a >= 2) ? kl : kh;
                *(uint4*)(tp + koff2 + a * 16384 + swz((uint32_t)(row * 128 + sg * 16))) =
                    *(const uint4*)(bsrc + (size_t)(kvrow0 + row) * KVDIM + kvh * HD + (a & 1) * 64 + sg * 8);
            }
        }
        FENCE_ASYNC_SHARED();
        __syncthreads();

        MBARRIER_WAIT_PARITY(hdr + 24, (uint32_t)(kt & 1));
    }

    TCGEN05_FENCE_AFTER();
    sums[half * 128 + sp * 32 + lane] = psum;
    __syncthreads();
    if (wid < 4) {
        const int row = wid * 32 + lane;
        float inv = 1.f / (sums[row] + sums[128 + row]);
        uint32_t* hrow = (uint32_t*)(aoh + (size_t)(qrow0 + row) * DIM + h * HD);
        uint32_t* lrow = (uint32_t*)(aol + (size_t)(qrow0 + row) * DIM + h * HD);
#pragma unroll
        for (int g = 0; g < 4; g++) {
            uint32_t r[32];
            TCGEN05_LD_X32(r, O_T + g * 32);
            TCGEN05_WAIT_LD();
            float* f = (float*)r;
#pragma unroll
            for (int j = 0; j < 16; j++) {
                float v0 = f[2 * j] * inv, v1 = f[2 * j + 1] * inv;
                __nv_bfloat16 h0 = __float2bfloat16(v0);
                __nv_bfloat16 h1 = __float2bfloat16(v1);
                __nv_bfloat162 hp(h0, h1);
                __nv_bfloat162 lp(__float2bfloat16(v0 - __bfloat162float(h0)),
                                  __float2bfloat16(v1 - __bfloat162float(h1)));
                hrow[g * 16 + j] = *(uint32_t*)&hp;
                lrow[g * 16 + j] = *(uint32_t*)&lp;
            }
        }
    }
    __syncthreads();
    if (wid == 0) { TCGEN05_RELINQ(); TCGEN05_DEALLOC(tmem, 512); }
#else
    // naive fallback (never selected)
    if (tid < 128) {
        int grow = qrow0 + tid;
        float acc[128];
        for (int d = 0; d < 128; d++) acc[d] = 0.f;
        float l = 0.f;
        for (int kv = 0; kv < SEQ; kv++) {
            float s = 0.f;
            size_t ko = (size_t)(b * SEQ + kv) * KVDIM + kvh * HD;
            size_t qo = (size_t)grow * DIM + h * HD;
            for (int d = 0; d < 128; d++)
                s += (__bfloat162float(qh[qo+d]) + __bfloat162float(ql[qo+d])) *
                     (__bfloat162float(kh[ko+d]) + __bfloat162float(kl[ko+d]));
            float p = __expf(s);
            l += p;
            for (int d = 0; d < 128; d++) {
                size_t vo = ((size_t)((b * NKV + kvh) * HD + d)) * SEQ + kv;
                acc[d] += p * (__bfloat162float(vth[vo]) + __bfloat162float(vtl[vo]));
            }
        }
        for (int d = 0; d < 128; d++) {
            float val = acc[d] / l;
            __nv_bfloat16 hh = __float2bfloat16(val);
            size_t o = (size_t)grow * DIM + h * HD + d;
            aoh[o] = hh;
            aol[o] = __float2bfloat16(val - __bfloat162float(hh));
        }
    }
#endif
}

// -----------------------------------------------------------------------------
extern "C" void kernel_launch(void* const* d_in, const int* in_sizes, int n_in,
                              void* d_out, int out_size) {
    const float* x   = (const float*)d_in[0];
    const float* Wq  = (const float*)d_in[1];
    const float* Wk  = (const float*)d_in[2];
    const float* Wv  = (const float*)d_in[3];
    const float* Wo  = (const float*)d_in[4];
    const float* qnw = (const float*)d_in[5];
    const float* knw = (const float*)d_in[6];
    float* out = (float*)d_out;

    float *q, *k, *v, *ct, *st;
    cudaGetSymbolAddress((void**)&q,  g_q);
    cudaGetSymbolAddress((void**)&k,  g_k);
    cudaGetSymbolAddress((void**)&v,  g_v);
    cudaGetSymbolAddress((void**)&ct, g_ct);
    cudaGetSymbolAddress((void**)&st, g_st);
    __nv_bfloat16 *xh,*xl,*aoh,*aol,*wqh,*wql,*wkh,*wkl,*wvh,*wvl,*woh,*wol;
    __nv_bfloat16 *qbh,*qbl,*kbh,*kbl,*vth,*vtl;
    cudaGetSymbolAddress((void**)&xh,  g_xh);  cudaGetSymbolAddress((void**)&xl,  g_xl);
    cudaGetSymbolAddress((void**)&aoh, g_aoh); cudaGetSymbolAddress((void**)&aol, g_aol);
    cudaGetSymbolAddress((void**)&wqh, g_wqh); cudaGetSymbolAddress((void**)&wql, g_wql);
    cudaGetSymbolAddress((void**)&wkh, g_wkh); cudaGetSymbolAddress((void**)&wkl, g_wkl);
    cudaGetSymbolAddress((void**)&wvh, g_wvh); cudaGetSymbolAddress((void**)&wvl, g_wvl);
    cudaGetSymbolAddress((void**)&woh, g_woh); cudaGetSymbolAddress((void**)&wol, g_wol);
    cudaGetSymbolAddress((void**)&qbh, g_qbh); cudaGetSymbolAddress((void**)&qbl, g_qbl);
    cudaGetSymbolAddress((void**)&kbh, g_kbh); cudaGetSymbolAddress((void**)&kbl, g_kbl);
    cudaGetSymbolAddress((void**)&vth, g_vth); cudaGetSymbolAddress((void**)&vtl, g_vtl);

    cudaFuncSetAttribute(gemm_qkv, cudaFuncAttributeMaxDynamicSharedMemorySize, GEMM_SMEM);
    cudaFuncSetAttribute(gemm_pre, cudaFuncAttributeMaxDynamicSharedMemorySize, GEMM_SMEM);
    cudaFuncSetAttribute(flash_tc, cudaFuncAttributeMaxDynamicSharedMemorySize, FL_SMEM);

    // #1: RoPE tables (the only FP64 left, 131k threads once)
    rope_tab<<<SEQ * 64 / 128, 128>>>(ct, st);
    // #2: weight transposes
    prep_w<<<dim3(64, 64, 4), 256>>>(Wq, Wk, Wv, Wo,
                                     wqh, wql, wkh, wkl, wvh, wvl, woh, wol);
    // #3: x conversion
    prep_x<<<4096, 256>>>(x, xh, xl);
    // #4: Q/K/V projections  (ncu-captured position)
    gemm_qkv<<<dim3(24, 32), 512, GEMM_SMEM>>>(xh, xl, wqh, wql, wkh, wkl,
                                               wvh, wvl, q, k, v);
    // #5: norm + rope (table) + V transpose
    normropev<<<dim3(MROWS, NH + NKV + 4), 128>>>(q, k, v, qnw, knw, ct, st,
                                                  qbh, qbl, kbh, kbl, vth, vtl);
    // #6: flash attention -> aoh/aol directly
    flash_tc<<<dim3(SEQ / 128, NH, BATCH), 256, FL_SMEM>>>(qbh, qbl, kbh, kbl,
                                                           vth, vtl, aoh, aol);
    // #7: output projection
    gemm_pre<<<dim3(16, 32), 512, GEMM_SMEM>>>(aoh, aol, woh, wol, out, DIM, DIM);
}

// round 8
// speedup vs baseline: 6.0408x; 1.0616x over previous
#include <cuda_runtime.h>
#include <cuda_bf16.h>
#include <math.h>
#include <stdint.h>

#define BATCH 2
#define SEQ   2048
#define DIM   2048
#define NH    16
#define NKV   4
#define HD    128
#define MROWS (BATCH*SEQ)
#define KVDIM (NKV*HD)

#if defined(__CUDA_ARCH__) && defined(__CUDA_ARCH_FEAT_SM103_ALL)
#define HAVE_TC 1
#else
#define HAVE_TC 0
#endif

// ---------------- scratch ---------------------------------------------------
__device__ float g_q [MROWS*DIM];
__device__ float g_k [MROWS*KVDIM];
__device__ float g_v [MROWS*KVDIM];
__device__ float g_ct[SEQ*64], g_st[SEQ*64];
__device__ __nv_bfloat16 g_xh [MROWS*DIM],   g_xl [MROWS*DIM];
__device__ __nv_bfloat16 g_aoh[MROWS*DIM],   g_aol[MROWS*DIM];
__device__ __nv_bfloat16 g_wqh[DIM*DIM],     g_wql[DIM*DIM];
__device__ __nv_bfloat16 g_wkh[KVDIM*DIM],   g_wkl[KVDIM*DIM];
__device__ __nv_bfloat16 g_wvh[KVDIM*DIM],   g_wvl[KVDIM*DIM];
__device__ __nv_bfloat16 g_woh[DIM*DIM],     g_wol[DIM*DIM];
__device__ __nv_bfloat16 g_qbh[MROWS*DIM],   g_qbl[MROWS*DIM];
__device__ __nv_bfloat16 g_kbh[MROWS*KVDIM], g_kbl[MROWS*KVDIM];
__device__ __nv_bfloat16 g_vth[MROWS*KVDIM], g_vtl[MROWS*KVDIM]; // V^T [b][kv][d][s]

__device__ __forceinline__ uint32_t swz(uint32_t off) {
    return off ^ ((off >> 3) & 0x70u);
}

#if HAVE_TC
__device__ __forceinline__ uint32_t smem_u32(const void* p) {
    uint32_t a;
    asm("{ .reg .u64 t; cvta.to.shared.u64 t, %1; cvt.u32.u64 %0, t; }" : "=r"(a) : "l"(p));
    return a;
}
__device__ __forceinline__ uint32_t elect_one() {
    uint32_t pred;
    asm volatile("{ .reg .pred p; elect.sync _|p, 0xFFFFFFFF; selp.b32 %0,1,0,p; }" : "=r"(pred));
    return pred;
}
#define MBARRIER_INIT(addr, cnt) \
    asm volatile("mbarrier.init.shared.b64 [%0], %1;" :: "r"(addr), "r"(cnt) : "memory")
#define MBARRIER_WAIT_PARITY(addr, par) do {                                   \
    uint32_t _m = (addr), _p = (par), _d;                                      \
    asm volatile("{ .reg .pred p; mbarrier.try_wait.parity.acquire.cta.shared::cta.b64 p, [%1], %2; selp.b32 %0,1,0,p; }" \
                 : "=r"(_d) : "r"(_m), "r"(_p) : "memory");                    \
    if (!_d) {                                                                 \
        asm volatile("{ .reg .pred P1; WL_%=: mbarrier.try_wait.parity.acquire.cta.shared::cta.b64 P1, [%0], %1, 0x989680; @P1 bra.uni WD_%=; bra.uni WL_%=; WD_%=: }" \
                     :: "r"(_m), "r"(_p) : "memory");                          \
    }                                                                          \
} while (0)
#define TCGEN05_ALLOC(res, n) \
    asm volatile("tcgen05.alloc.cta_group::1.sync.aligned.shared::cta.b32 [%0], %1;" :: "r"(res), "r"(n) : "memory")
#define TCGEN05_DEALLOC(t, n) \
    asm volatile("tcgen05.dealloc.cta_group::1.sync.aligned.b32 %0, %1;" :: "r"(t), "r"(n))
#define TCGEN05_RELINQ() \
    asm volatile("tcgen05.relinquish_alloc_permit.cta_group::1.sync.aligned;")
#define TCGEN05_COMMIT(mb) \
    asm volatile("tcgen05.commit.cta_group::1.mbarrier::arrive::one.shared::cluster.b64 [%0];" :: "r"(mb) : "memory")
#define TCGEN05_FENCE_BEFORE() asm volatile("tcgen05.fence::before_thread_sync;" ::: "memory")
#define TCGEN05_FENCE_AFTER()  asm volatile("tcgen05.fence::after_thread_sync;" ::: "memory")
#define TCGEN05_WAIT_LD()      asm volatile("tcgen05.wait::ld.sync.aligned;" ::: "memory")
#define TCGEN05_WAIT_ST()      asm volatile("tcgen05.wait::st.sync.aligned;" ::: "memory")
#define FENCE_ASYNC_SHARED()   asm volatile("fence.proxy.async.shared::cta;" ::: "memory")
#define TCGEN05_LD_X32(r, a)                                                   \
    asm volatile("tcgen05.ld.sync.aligned.32x32b.x32.b32 "                     \
        "{%0,%1,%2,%3,%4,%5,%6,%7,%8,%9,%10,%11,%12,%13,%14,%15,"              \
        "%16,%17,%18,%19,%20,%21,%22,%23,%24,%25,%26,%27,%28,%29,%30,%31}, [%32];" \
        : "=r"((r)[0]),"=r"((r)[1]),"=r"((r)[2]),"=r"((r)[3]),                 \
          "=r"((r)[4]),"=r"((r)[5]),"=r"((r)[6]),"=r"((r)[7]),                 \
          "=r"((r)[8]),"=r"((r)[9]),"=r"((r)[10]),"=r"((r)[11]),               \
          "=r"((r)[12]),"=r"((r)[13]),"=r"((r)[14]),"=r"((r)[15]),             \
          "=r"((r)[16]),"=r"((r)[17]),"=r"((r)[18]),"=r"((r)[19]),             \
          "=r"((r)[20]),"=r"((r)[21]),"=r"((r)[22]),"=r"((r)[23]),             \
          "=r"((r)[24]),"=r"((r)[25]),"=r"((r)[26]),"=r"((r)[27]),             \
          "=r"((r)[28]),"=r"((r)[29]),"=r"((r)[30]),"=r"((r)[31])              \
        : "r"(a))
#define TCGEN05_ST_X16(a, r)                                                   \
    asm volatile("tcgen05.st.sync.aligned.32x32b.x16.b32 [%0], "               \
        "{%1,%2,%3,%4,%5,%6,%7,%8,%9,%10,%11,%12,%13,%14,%15,%16};"            \
        :: "r"(a),                                                             \
           "r"((r)[0]),"r"((r)[1]),"r"((r)[2]),"r"((r)[3]),                    \
           "r"((r)[4]),"r"((r)[5]),"r"((r)[6]),"r"((r)[7]),                    \
           "r"((r)[8]),"r"((r)[9]),"r"((r)[10]),"r"((r)[11]),                  \
           "r"((r)[12]),"r"((r)[13]),"r"((r)[14]),"r"((r)[15])                 \
        : "memory")
#define TCGEN05_ST_X32(a, r)                                                   \
    asm volatile("tcgen05.st.sync.aligned.32x32b.x32.b32 [%0], "               \
        "{%1,%2,%3,%4,%5,%6,%7,%8,%9,%10,%11,%12,%13,%14,%15,%16,"             \
        "%17,%18,%19,%20,%21,%22,%23,%24,%25,%26,%27,%28,%29,%30,%31,%32};"    \
        :: "r"(a),                                                             \
           "r"((r)[0]),"r"((r)[1]),"r"((r)[2]),"r"((r)[3]),                    \
           "r"((r)[4]),"r"((r)[5]),"r"((r)[6]),"r"((r)[7]),                    \
           "r"((r)[8]),"r"((r)[9]),"r"((r)[10]),"r"((r)[11]),                  \
           "r"((r)[12]),"r"((r)[13]),"r"((r)[14]),"r"((r)[15]),                \
           "r"((r)[16]),"r"((r)[17]),"r"((r)[18]),"r"((r)[19]),                \
           "r"((r)[20]),"r"((r)[21]),"r"((r)[22]),"r"((r)[23]),                \
           "r"((r)[24]),"r"((r)[25]),"r"((r)[26]),"r"((r)[27]),                \
           "r"((r)[28]),"r"((r)[29]),"r"((r)[30]),"r"((r)[31])                 \
        : "memory")

__device__ __forceinline__ uint64_t make_desc(uint32_t addr) {
    return ((uint64_t)2u << 61) | ((uint64_t)1u << 46)
         | ((uint64_t)64u << 32) | ((uint64_t)1u << 16)
         | ((uint64_t)(addr >> 4) & 0x3FFFu);
}
__device__ __forceinline__ void mma_f16_ss(uint32_t d, uint64_t a, uint64_t b,
                                           uint32_t idesc, uint32_t en) {
    asm volatile("{ .reg .pred p; setp.ne.u32 p, %5, 0;\n\t"
        "tcgen05.mma.cta_group::1.kind::f16 [%0], %1, %2, %3, {%4,%4,%4,%4}, p; }"
        :: "r"(d), "l"(a), "l"(b), "r"(idesc), "r"(0u), "r"(en) : "memory");
}
__device__ __forceinline__ void mma_f16_ts(uint32_t d, uint32_t a, uint64_t b,
                                           uint32_t idesc, uint32_t en) {
    asm volatile("{ .reg .pred p; setp.ne.u32 p, %5, 0;\n\t"
        "tcgen05.mma.cta_group::1.kind::f16 [%0], [%1], %2, %3, {%4,%4,%4,%4}, p; }"
        :: "r"(d), "r"(a), "l"(b), "r"(idesc), "r"(0u), "r"(en) : "memory");
}
#define GEMM_IDESC (0x490u | (16u << 17) | (8u << 24))  // F32 acc, bf16, M=128, N=128
#endif // HAVE_TC

// ---------------- prep: weights transpose + x convert + rope tables ---------
// grid (64, 64, 6), 256 thr.
__global__ __launch_bounds__(256) void prep(const float* __restrict__ Wq,
                                            const float* __restrict__ Wk,
                                            const float* __restrict__ Wv,
                                            const float* __restrict__ Wo,
                                            const float* __restrict__ x,
                                            __nv_bfloat16* __restrict__ wqh, __nv_bfloat16* __restrict__ wql,
                                            __nv_bfloat16* __restrict__ wkh, __nv_bfloat16* __restrict__ wkl,
                                            __nv_bfloat16* __restrict__ wvh, __nv_bfloat16* __restrict__ wvl,
                                            __nv_bfloat16* __restrict__ woh, __nv_bfloat16* __restrict__ wol,
                                            __nv_bfloat16* __restrict__ xh,  __nv_bfloat16* __restrict__ xl,
                                            float* __restrict__ ct, float* __restrict__ st) {
    const int z = blockIdx.z;
    const int tid = threadIdx.x;
    if (z == 4) {            // x conversion
        int base = (blockIdx.y * 64 + blockIdx.x) * 256 + tid;
#pragma unroll
        for (int rep = 0; rep < 2; rep++) {
            int i = base + rep * 1048576;
            float4 v = *(const float4*)(x + (size_t)i * 4);
            __nv_bfloat16 h0 = __float2bfloat16(v.x), h1 = __float2bfloat16(v.y);
            __nv_bfloat16 h2 = __float2bfloat16(v.z), h3 = __float2bfloat16(v.w);
            __nv_bfloat162 hA(h0, h1), hB(h2, h3);
            __nv_bfloat162 lA(__float2bfloat16(v.x - __bfloat162float(h0)),
                              __float2bfloat16(v.y - __bfloat162float(h1)));
            __nv_bfloat162 lB(__float2bfloat16(v.z - __bfloat162float(h2)),
                              __float2bfloat16(v.w - __bfloat162float(h3)));
            *(uint2*)(xh + (size_t)i * 4) = make_uint2(*(uint32_t*)&hA, *(uint32_t*)&hB);
            *(uint2*)(xl + (size_t)i * 4) = make_uint2(*(uint32_t*)&lA, *(uint32_t*)&lB);
        }
        return;
    }
    if (z == 5) {            // rope tables
        int blk = blockIdx.y * 64 + blockIdx.x;
        if (blk >= 512) return;
        int i = blk * 256 + tid;
        int s = i >> 6, j = i & 63;
        float invf  = (float)exp(-9.210340371976184 * ((double)(2 * j) * (1.0 / 128.0)));
        float theta = (float)s * invf;
        double td = (double)theta;
        ct[i] = (float)cos(td);
        st[i] = (float)sin(td);
        return;
    }
    const float* W;
    __nv_bfloat16 *th, *tl;
    int N;
    if      (z == 0) { W = Wq; th = wqh; tl = wql; N = DIM;   }
    else if (z == 1) { W = Wk; th = wkh; tl = wkl; N = KVDIM; }
    else if (z == 2) { W = Wv; th = wvh; tl = wvl; N = KVDIM; }
    else             { W = Wo; th = woh; tl = wol; N = DIM;   }
    const int n0 = blockIdx.x * 32, k0 = blockIdx.y * 32;
    if (n0 >= N) return;
    __shared__ float smt[32][33];
    const int tx = tid & 31, ty = tid >> 5;
#pragma unroll
    for (int i = 0; i < 4; i++)
        smt[ty + 8 * i][tx] = W[(size_t)(k0 + ty + 8 * i) * N + n0 + tx];
    __syncthreads();
#pragma unroll
    for (int i = 0; i < 4; i++) {
        int nl = ty + 8 * i;
        float f = smt[tx][nl];
        __nv_bfloat16 h = __float2bfloat16(f);
        th[(size_t)(n0 + nl) * DIM + k0 + tx] = h;
        tl[(size_t)(n0 + nl) * DIM + k0 + tx] = __float2bfloat16(f - __bfloat162float(h));
    }
}

// ---------------- GEMM core: 128x256 C-tile, bf16x3, 512 threads ------------
// smem buf/chunk: Ah 16K | Al 16K | Bh 32K | Bl 32K = 96KB, double-buffered.
#define GEMM_SMEM (1024 + 2*98304)
#if HAVE_TC
__device__ __forceinline__ void gemm_body256(const __nv_bfloat16* ah, const __nv_bfloat16* al,
                                             const __nv_bfloat16* bh, const __nv_bfloat16* bl,
                                             float* C, int N, int K, int m0, int n0,
                                             char* smem) {
    const uint32_t sb   = smem_u32(smem);
    const uint32_t base = (sb + 1023u) & ~1023u;
    const uint32_t hdr  = base;
    const uint32_t tile = base + 1024;
    char* tp = smem + (tile - sb);
    const int tid = threadIdx.x, wid = tid >> 5, lane = tid & 31;

    if (wid == 0) TCGEN05_ALLOC(hdr, 256);
    if (tid == 0) { MBARRIER_INIT(hdr + 16, 1); MBARRIER_INIT(hdr + 24, 1); }
    __syncthreads();
    uint32_t tmem;
    asm volatile("ld.shared.b32 %0, [%1];" : "=r"(tmem) : "r"(hdr));

    const int NC = K >> 6;
    for (int c = 0; c < NC; c++) {
        const int buf = c & 1, boff = buf * 98304, k0 = c << 6;
        if (c >= 2)
            MBARRIER_WAIT_PARITY(hdr + 16 + 8 * buf, (uint32_t)(((c >> 1) - 1) & 1));
#pragma unroll
        for (int i = 0; i < 12; i++) {
            int s = tid + (i << 9);
            const __nv_bfloat16* src;
            uint32_t dst;
            if (s < 1024) {
                int row = s >> 3, sg = s & 7;
                src = ah + (size_t)(m0 + row) * K + k0 + sg * 8;
                dst = swz((uint32_t)(s << 4));
            } else if (s < 2048) {
                int t = s - 1024, row = t >> 3, sg = t & 7;
                src = al + (size_t)(m0 + row) * K + k0 + sg * 8;
                dst = 16384u + swz((uint32_t)(t << 4));
            } else if (s < 4096) {
                int t = s - 2048, row = t >> 3, sg = t & 7;
                src = bh + (size_t)(n0 + row) * K + k0 + sg * 8;
                dst = 32768u + swz((uint32_t)(t << 4));
            } else {
                int t = s - 4096, row = t >> 3, sg = t & 7;
                src = bl + (size_t)(n0 + row) * K + k0 + sg * 8;
                dst = 65536u + swz((uint32_t)(t << 4));
            }
            *(uint4*)(tp + boff + dst) = *(const uint4*)src;
        }
        FENCE_ASYNC_SHARED();
        __syncthreads();
        if (wid == 0 && elect_one()) {
            uint64_t dah = make_desc(tile + boff);
            uint64_t dal = make_desc(tile + boff + 16384);
#pragma unroll
            for (int nh = 0; nh < 2; nh++) {
                uint64_t dbh = make_desc(tile + boff + 32768 + nh * 16384);
                uint64_t dbl = make_desc(tile + boff + 65536 + nh * 16384);
                uint32_t acc = tmem + nh * 128;
#pragma unroll
                for (int s = 0; s < 4; s++) {
                    uint32_t en0 = (c == 0 && s == 0) ? 0u : 1u;
                    mma_f16_ss(acc, dah + s * 2, dbh + s * 2, GEMM_IDESC, en0);
                    mma_f16_ss(acc, dah + s * 2, dbl + s * 2, GEMM_IDESC, 1u);
                    mma_f16_ss(acc, dal + s * 2, dbh + s * 2, GEMM_IDESC, 1u);
                }
            }
            TCGEN05_COMMIT(hdr + 16 + 8 * buf);
        }
    }
    MBARRIER_WAIT_PARITY(hdr + 16 + 8 * ((NC - 1) & 1), (uint32_t)(((NC - 1) >> 1) & 1));
    TCGEN05_FENCE_AFTER();
    if (wid < 4) {
#pragma unroll
        for (int nh = 0; nh < 2; nh++) {
            float* crow = C + (size_t)(m0 + wid * 32 + lane) * N + n0 + nh * 128;
#pragma unroll
            for (int g = 0; g < 4; g++) {
                uint32_t r[32];
                TCGEN05_LD_X32(r, tmem + nh * 128 + g * 32);
                TCGEN05_WAIT_LD();
                float* f = (float*)r;
#pragma unroll
                for (int q4 = 0; q4 < 8; q4++)
                    *(float4*)(crow + g * 32 + q4 * 4) =
                        make_float4(f[q4*4], f[q4*4+1], f[q4*4+2], f[q4*4+3]);
            }
        }
    }
    __syncthreads();
    if (wid == 0) { TCGEN05_RELINQ(); TCGEN05_DEALLOC(tmem, 256); }
}
#endif

// Q/K/V projections: grid (12, 32), 512 thr.  bx<8: Q, 8-9: K, 10-11: V.
__global__ __launch_bounds__(512) void gemm_qkv(const __nv_bfloat16* __restrict__ ah,
                                                const __nv_bfloat16* __restrict__ al,
                                                const __nv_bfloat16* __restrict__ bhq,
                                                const __nv_bfloat16* __restrict__ blq,
                                                const __nv_bfloat16* __restrict__ bhk,
                                                const __nv_bfloat16* __restrict__ blk_,
                                                const __nv_bfloat16* __restrict__ bhv,
                                                const __nv_bfloat16* __restrict__ blv,
                                                float* __restrict__ cq,
                                                float* __restrict__ ck,
                                                float* __restrict__ cv) {
    const int bx = blockIdx.x;
    const __nv_bfloat16 *bh, *bl;
    float* C;
    int N, nb;
    if      (bx < 8)  { bh = bhq; bl = blq;  C = cq; N = DIM;   nb = bx;      }
    else if (bx < 10) { bh = bhk; bl = blk_; C = ck; N = KVDIM; nb = bx - 8;  }
    else              { bh = bhv; bl = blv;  C = cv; N = KVDIM; nb = bx - 10; }
#if HAVE_TC
    extern __shared__ char smem[];
    gemm_body256(ah, al, bh, bl, C, N, DIM, blockIdx.y * 128, nb * 256, smem);
#else
    const int tid = threadIdx.x;
    const int m0 = blockIdx.y * 128, n0 = nb * 256;
    for (int e = tid; e < 128 * 256; e += 512) {
        int i = e >> 8, j = e & 255;
        float acc = 0.f;
        for (int kk = 0; kk < DIM; kk++)
            acc += (__bfloat162float(ah[(size_t)(m0+i)*DIM+kk]) + __bfloat162float(al[(size_t)(m0+i)*DIM+kk])) *
                   (__bfloat162float(bh[(size_t)(n0+j)*DIM+kk]) + __bfloat162float(bl[(size_t)(n0+j)*DIM+kk]));
        C[(size_t)(m0 + i) * N + n0 + j] = acc;
    }
#endif
}

// output projection: grid (8, 32), 512 thr.
__global__ __launch_bounds__(512) void gemm_pre(const __nv_bfloat16* __restrict__ ah,
                                                const __nv_bfloat16* __restrict__ al,
                                                const __nv_bfloat16* __restrict__ bh,
                                                const __nv_bfloat16* __restrict__ bl,
                                                float* __restrict__ C, int N, int K) {
#if HAVE_TC
    extern __shared__ char smem[];
    gemm_body256(ah, al, bh, bl, C, N, K, blockIdx.y * 128, blockIdx.x * 256, smem);
#else
    const int tid = threadIdx.x;
    const int m0 = blockIdx.y * 128, n0 = blockIdx.x * 256;
    for (int e = tid; e < 128 * 256; e += 512) {
        int i = e >> 8, j = e & 255;
        float acc = 0.f;
        for (int kk = 0; kk < K; kk++)
            acc += (__bfloat162float(ah[(size_t)(m0+i)*K+kk]) + __bfloat162float(al[(size_t)(m0+i)*K+kk])) *
                   (__bfloat162float(bh[(size_t)(n0+j)*K+kk]) + __bfloat162float(bl[(size_t)(n0+j)*K+kk]));
        C[(size_t)(m0 + i) * N + n0 + j] = acc;
    }
#endif
}

// ---------------- normrope (table-driven) + V transpose ----------------------
__global__ __launch_bounds__(128) void normropev(const float* __restrict__ q,
                                                 const float* __restrict__ k,
                                                 const float* __restrict__ v,
                                                 const float* __restrict__ qw,
                                                 const float* __restrict__ kw,
                                                 const float* __restrict__ ct,
                                                 const float* __restrict__ st,
                                                 __nv_bfloat16* __restrict__ qbh,
                                                 __nv_bfloat16* __restrict__ qbl,
                                                 __nv_bfloat16* __restrict__ kbh,
                                                 __nv_bfloat16* __restrict__ kbl,
                                                 __nv_bfloat16* __restrict__ vh,
                                                 __nv_bfloat16* __restrict__ vl) {
    const int row = blockIdx.x, hy = blockIdx.y, d = threadIdx.x;

    if (hy >= NH + NKV) {
        int vb = (hy - (NH + NKV)) * MROWS + row;
        int o = vb * 128 + d;
        int s = o & (SEQ - 1);
        int rest = o >> 11;
        int dd = rest & (HD - 1);
        int bkv = rest >> 7;
        int b = bkv >> 2, kv = bkv & 3;
        float f = v[(size_t)(b * SEQ + s) * KVDIM + kv * HD + dd];
        __nv_bfloat16 h = __float2bfloat16(f);
        vh[o] = h;
        vl[o] = __float2bfloat16(f - __bfloat162float(h));
        return;
    }

    const int s = row & (SEQ - 1);
    const float* p;
    const float* w;
    if (hy < NH) { p = q + (size_t)row * DIM   + hy * HD;        w = qw; }
    else         { p = k + (size_t)row * KVDIM + (hy - NH) * HD; w = kw; }

    float x = p[d];
    float v2 = x * x;
#pragma unroll
    for (int off = 16; off > 0; off >>= 1)
        v2 += __shfl_xor_sync(0xffffffffu, v2, off);
    __shared__ float wsum[4];
    const int lane = d & 31, wrp = d >> 5;
    if (lane == 0) wsum[wrp] = v2;
    __syncthreads();
    float total = wsum[0] + wsum[1] + wsum[2] + wsum[3];
    float rn = rsqrtf(total * (1.0f / 128.0f) + 1e-6f);
    float nx = x * rn * w[d];
    __shared__ float sn[128];
    sn[d] = nx;
    __syncthreads();

    const int j = d & 63;
    float c  = ct[s * 64 + j];
    float si = st[s * 64 + j];
    float out = (d < 64) ? (nx * c - sn[d + 64] * si)
                         : (nx * c + sn[d - 64] * si);
    if (hy < NH) {
        float o2 = out * 0.08838834764831843f;
        __nv_bfloat16 hh = __float2bfloat16(o2);
        size_t o = (size_t)row * DIM + hy * HD + d;
        qbh[o] = hh;
        qbl[o] = __float2bfloat16(o2 - __bfloat162float(hh));
    } else {
        __nv_bfloat16 hh = __float2bfloat16(out);
        size_t o = (size_t)row * KVDIM + (hy - NH) * HD + d;
        kbh[o] = hh;
        kbl[o] = __float2bfloat16(out - __bfloat162float(hh));
    }
}

// ---------------- flash attention: tensor-pipe-chained tcgen05 --------------
// grid (SEQ/128, NH, BATCH), 256 thr.
// smem: hdr 1024 | sums 1024 | Kbuf0 64KB | Kbuf1 64KB | Vbuf 64KB
// TMEM: Q@0(128: hi 0-63, lo 64-127), S@128, O@256, PH@384, PL@448
#define FL_SMEM (1024 + 2048 + 3*65536)
__global__ __launch_bounds__(256) void flash_tc(const __nv_bfloat16* __restrict__ qh,
                                                const __nv_bfloat16* __restrict__ ql,
                                                const __nv_bfloat16* __restrict__ kh,
                                                const __nv_bfloat16* __restrict__ kl,
                                                const __nv_bfloat16* __restrict__ vth,
                                                const __nv_bfloat16* __restrict__ vtl,
                                                __nv_bfloat16* __restrict__ aoh,
                                                __nv_bfloat16* __restrict__ aol) {
    const int qt = blockIdx.x, h = blockIdx.y, b = blockIdx.z;
    const int kvh = h >> 2, tid = threadIdx.x;
    const int qrow0 = b * SEQ + qt * 128;
#if HAVE_TC
    extern __shared__ char smem[];
    const uint32_t sb   = smem_u32(smem);
    const uint32_t base = (sb + 1023u) & ~1023u;
    const uint32_t hdr  = base;
    const uint32_t tile = base + 2048;
    char* tp = smem + (tile - sb);
    float* sums = (float*)(smem + (base + 1024 - sb));   // [2][128]
    const int wid = tid >> 5, lane = tid & 31;
    const int sp = wid & 3, half = wid >> 2;

    if (wid == 0) TCGEN05_ALLOC(hdr, 512);
    if (tid == 0) { MBARRIER_INIT(hdr + 16, 1); MBARRIER_INIT(hdr + 24, 1); }
    __syncthreads();
    uint32_t tmem;
    asm volatile("ld.shared.b32 %0, [%1];" : "=r"(tmem) : "r"(hdr));
    const uint32_t Q_T = tmem, S_T = tmem + 128, O_T = tmem + 256;
    const uint32_t PH_T = tmem + 384, PL_T = tmem + 448;

    // ---- Q -> TMEM ----
    if (tid < 128) {
        const uint32_t woff = ((uint32_t)wid) << 21;
        uint32_t r[64];
        const uint4* srch = (const uint4*)(qh + (size_t)(qrow0 + tid) * DIM + h * HD);
#pragma unroll
        for (int i = 0; i < 16; i++) ((uint4*)r)[i] = srch[i];
        TCGEN05_ST_X32(Q_T + 0  + woff, r);
        TCGEN05_ST_X32(Q_T + 32 + woff, r + 32);
        const uint4* srcl = (const uint4*)(ql + (size_t)(qrow0 + tid) * DIM + h * HD);
#pragma unroll
        for (int i = 0; i < 16; i++) ((uint4*)r)[i] = srcl[i];
        TCGEN05_ST_X32(Q_T + 64 + woff, r);
        TCGEN05_ST_X32(Q_T + 96 + woff, r + 32);
        TCGEN05_WAIT_ST();
    }

    // ---- prologue: K(0) -> Kbuf0 ----
    {
        const int kvrow0 = b * SEQ;
#pragma unroll 4
        for (int i = 0; i < 16; i++) {
            int s = tid + (i << 8);
            int a = s >> 10, seg = s & 1023, row = seg >> 3, sg = seg & 7;
            const __nv_bfloat16* bsrc = (a >= 2) ? kl : kh;
            *(uint4*)(tp + a * 16384 + swz((uint32_t)(row * 128 + sg * 16))) =
                *(const uint4*)(bsrc + (size_t)(kvrow0 + row) * KVDIM + kvh * HD + (a & 1) * 64 + sg * 8);
        }
    }
    TCGEN05_FENCE_BEFORE();
    FENCE_ASYNC_SHARED();
    __syncthreads();

    // ---- issue S(0) ----
    if (wid == 0) {
        TCGEN05_FENCE_AFTER();
        if (elect_one()) {
#pragma unroll
            for (int st = 0; st < 8; st++) {
                uint32_t ahi = Q_T + st * 8, alo = Q_T + 64 + st * 8;
                uint64_t bhd = make_desc(tile + (st >> 2) * 16384) + (st & 3) * 2;
                uint64_t bld = make_desc(tile + 32768 + (st >> 2) * 16384) + (st & 3) * 2;
                mma_f16_ts(S_T, ahi, bhd, GEMM_IDESC, st > 0 ? 1u : 0u);
                mma_f16_ts(S_T, ahi, bld, GEMM_IDESC, 1u);
                mma_f16_ts(S_T, alo, bhd, GEMM_IDESC, 1u);
            }
            TCGEN05_COMMIT(hdr + 16);
        }
    }

    float psum = 0.f;

    for (int kt = 0; kt < SEQ / 128; kt++) {
        // ---- O(kt-1) must be done before V/P reuse ----
        if (kt > 0)
            MBARRIER_WAIT_PARITY(hdr + 24, (uint32_t)((kt - 1) & 1));

        // ---- copy V(kt) -> Vbuf (overlaps in-flight S(kt)) ----
        {
            const int vcol0 = kt * 128;
#pragma unroll 4
            for (int i = 0; i < 16; i++) {
                int s = tid + (i << 8);
                int a = s >> 10, seg = s & 1023, row = seg >> 3, sg = seg & 7;
                const __nv_bfloat16* bsrc = (a >= 2) ? vtl : vth;
                *(uint4*)(tp + 131072 + a * 16384 + swz((uint32_t)(row * 128 + sg * 16))) =
                    *(const uint4*)(bsrc + ((size_t)((b * NKV + kvh) * HD + row)) * SEQ
                                    + vcol0 + (a & 1) * 64 + sg * 8);
            }
        }
        // ---- copy K(kt+1) -> Kbuf((kt+1)&1) (buffer last read by S(kt-1)) ----
        if (kt < SEQ / 128 - 1) {
            const int kvrow0 = b * SEQ + (kt + 1) * 128;
            const uint32_t koff2 = (uint32_t)((kt + 1) & 1) * 65536u;
#pragma unroll 4
            for (int i = 0; i < 16; i++) {
                int s = tid + (i << 8);
                int a = s >> 10, seg = s & 1023, row = seg >> 3, sg = seg & 7;
                const __nv_bfloat16* bsrc = (a >= 2) ? kl : kh;
                *(uint4*)(tp + koff2 + a * 16384 + swz((uint32_t)(row * 128 + sg * 16))) =
                    *(const uint4*)(bsrc + (size_t)(kvrow0 + row) * KVDIM + kvh * HD + (a & 1) * 64 + sg * 8);
            }
        }
        FENCE_ASYNC_SHARED();

        // ---- wait S(kt), softmax (no max: |s| <= sqrt(128)), P -> TMEM ----
        MBARRIER_WAIT_PARITY(hdr + 16, (uint32_t)(kt & 1));
        TCGEN05_FENCE_AFTER();
        {
            float sum = 0.f;
            const uint32_t woff = ((uint32_t)sp) << 21;
#pragma unroll
            for (int gg = 0; gg < 2; gg++) {
                int g = half * 2 + gg;
                uint32_t r[32];
                TCGEN05_LD_X32(r, S_T + g * 32);
                TCGEN05_WAIT_LD();
                uint32_t hw[16], lw[16];
#pragma unroll
                for (int j = 0; j < 16; j++) {
                    float p0 = __expf(__uint_as_float(r[2 * j]));
                    float p1 = __expf(__uint_as_float(r[2 * j + 1]));
                    sum += p0 + p1;
                    __nv_bfloat16 h0 = __float2bfloat16(p0);
                    __nv_bfloat16 h1 = __float2bfloat16(p1);
                    __nv_bfloat162 hp(h0, h1);
                    __nv_bfloat162 lp(__float2bfloat16(p0 - __bfloat162float(h0)),
                                      __float2bfloat16(p1 - __bfloat162float(h1)));
                    hw[j] = *(uint32_t*)&hp;
                    lw[j] = *(uint32_t*)&lp;
                }
                TCGEN05_ST_X16(PH_T + g * 16 + woff, hw);
                TCGEN05_ST_X16(PL_T + g * 16 + woff, lw);
            }
            TCGEN05_WAIT_ST();
            psum += sum;
            TCGEN05_FENCE_BEFORE();
        }
        __syncthreads();   // P, V(kt), K(kt+1) all complete & visible

        // ---- issue O(kt), then S(kt+1) back-to-back on the tensor pipe ----
        if (wid == 0) {
            TCGEN05_FENCE_AFTER();
            if (elect_one()) {
#pragma unroll
                for (int st = 0; st < 8; st++) {
                    uint32_t ahi = PH_T + st * 8, alo = PL_T + st * 8;
                    uint64_t bhd = make_desc(tile + 131072 + (st >> 2) * 16384) + (st & 3) * 2;
                    uint64_t bld = make_desc(tile + 131072 + 32768 + (st >> 2) * 16384) + (st & 3) * 2;
                    uint32_t en0 = (kt == 0 && st == 0) ? 0u : 1u;
                    mma_f16_ts(O_T, ahi, bhd, GEMM_IDESC, en0);
                    mma_f16_ts(O_T, ahi, bld, GEMM_IDESC, 1u);
                    mma_f16_ts(O_T, alo, bhd, GEMM_IDESC, 1u);
                }
                TCGEN05_COMMIT(hdr + 24);
                if (kt < SEQ / 128 - 1) {
                    const uint32_t koff2 = (uint32_t)((kt + 1) & 1) * 65536u;
#pragma unroll
                    for (int st = 0; st < 8; st++) {
                        uint32_t ahi = Q_T + st * 8, alo = Q_T + 64 + st * 8;
                        uint64_t bhd = make_desc(tile + koff2 + (st >> 2) * 16384) + (st & 3) * 2;
                        uint64_t bld = make_desc(tile + koff2 + 32768 + (st >> 2) * 16384) + (st & 3) * 2;
                        mma_f16_ts(S_T, ahi, bhd, GEMM_IDESC, st > 0 ? 1u : 0u);
                        mma_f16_ts(S_T, ahi, bld, GEMM_IDESC, 1u);
                        mma_f16_ts(S_T, alo, bhd, GEMM_IDESC, 1u);
                    }
                    TCGEN05_COMMIT(hdr + 16);
                }
            }
        }
    }

    MBARRIER_WAIT_PARITY(hdr + 24, 1u);   // O(15), commit #16 -> parity 1
    TCGEN05_FENCE_AFTER();
    sums[half * 128 + sp * 32 + lane] = psum;
    __syncthreads();
    if (wid < 4) {
        const int row = wid * 32 + lane;
        float inv = 1.f / (sums[row] + sums[128 + row]);
        uint32_t* hrow = (uint32_t*)(aoh + (size_t)(qrow0 + row) * DIM + h * HD);
        uint32_t* lrow = (uint32_t*)(aol + (size_t)(qrow0 + row) * DIM + h * HD);
#pragma unroll
        for (int g = 0; g < 4; g++) {
            uint32_t r[32];
            TCGEN05_LD_X32(r, O_T + g * 32);
            TCGEN05_WAIT_LD();
            float* f = (float*)r;
#pragma unroll
            for (int j = 0; j < 16; j++) {
                float v0 = f[2 * j] * inv, v1 = f[2 * j + 1] * inv;
                __nv_bfloat16 h0 = __float2bfloat16(v0);
                __nv_bfloat16 h1 = __float2bfloat16(v1);
                __nv_bfloat162 hp(h0, h1);
                __nv_bfloat162 lp(__float2bfloat16(v0 - __bfloat162float(h0)),
                                  __float2bfloat16(v1 - __bfloat162float(h1)));
                hrow[g * 16 + j] = *(uint32_t*)&hp;
                lrow[g * 16 + j] = *(uint32_t*)&lp;
            }
        }
    }
    __syncthreads();
    if (wid == 0) { TCGEN05_RELINQ(); TCGEN05_DEALLOC(tmem, 512); }
#else
    // naive fallback (never selected)
    if (tid < 128) {
        int grow = qrow0 + tid;
        float acc[128];
        for (int d = 0; d < 128; d++) acc[d] = 0.f;
        float l = 0.f;
        for (int kv = 0; kv < SEQ; kv++) {
            float s = 0.f;
            size_t ko = (size_t)(b * SEQ + kv) * KVDIM + kvh * HD;
            size_t qo = (size_t)grow * DIM + h * HD;
            for (int d = 0; d < 128; d++)
                s += (__bfloat162float(qh[qo+d]) + __bfloat162float(ql[qo+d])) *
                     (__bfloat162float(kh[ko+d]) + __bfloat162float(kl[ko+d]));
            float p = __expf(s);
            l += p;
            for (int d = 0; d < 128; d++) {
                size_t vo = ((size_t)((b * NKV + kvh) * HD + d)) * SEQ + kv;
                acc[d] += p * (__bfloat162float(vth[vo]) + __bfloat162float(vtl[vo]));
            }
        }
        for (int d = 0; d < 128; d++) {
            float val = acc[d] / l;
            __nv_bfloat16 hh = __float2bfloat16(val);
            size_t o = (size_t)grow * DIM + h * HD + d;
            aoh[o] = hh;
            aol[o] = __float2bfloat16(val - __bfloat162float(hh));
        }
    }
#endif
}

// -----------------------------------------------------------------------------
extern "C" void kernel_launch(void* const* d_in, const int* in_sizes, int n_in,
                              void* d_out, int out_size) {
    const float* x   = (const float*)d_in[0];
    const float* Wq  = (const float*)d_in[1];
    const float* Wk  = (const float*)d_in[2];
    const float* Wv  = (const float*)d_in[3];
    const float* Wo  = (const float*)d_in[4];
    const float* qnw = (const float*)d_in[5];
    const float* knw = (const float*)d_in[6];
    float* out = (float*)d_out;

    float *q, *k, *v, *ct, *st;
    cudaGetSymbolAddress((void**)&q,  g_q);
    cudaGetSymbolAddress((void**)&k,  g_k);
    cudaGetSymbolAddress((void**)&v,  g_v);
    cudaGetSymbolAddress((void**)&ct, g_ct);
    cudaGetSymbolAddress((void**)&st, g_st);
    __nv_bfloat16 *xh,*xl,*aoh,*aol,*wqh,*wql,*wkh,*wkl,*wvh,*wvl,*woh,*wol;
    __nv_bfloat16 *qbh,*qbl,*kbh,*kbl,*vth,*vtl;
    cudaGetSymbolAddress((void**)&xh,  g_xh);  cudaGetSymbolAddress((void**)&xl,  g_xl);
    cudaGetSymbolAddress((void**)&aoh, g_aoh); cudaGetSymbolAddress((void**)&aol, g_aol);
    cudaGetSymbolAddress((void**)&wqh, g_wqh); cudaGetSymbolAddress((void**)&wql, g_wql);
    cudaGetSymbolAddress((void**)&wkh, g_wkh); cudaGetSymbolAddress((void**)&wkl, g_wkl);
    cudaGetSymbolAddress((void**)&wvh, g_wvh); cudaGetSymbolAddress((void**)&wvl, g_wvl);
    cudaGetSymbolAddress((void**)&woh, g_woh); cudaGetSymbolAddress((void**)&wol, g_wol);
    cudaGetSymbolAddress((void**)&qbh, g_qbh); cudaGetSymbolAddress((void**)&qbl, g_qbl);
    cudaGetSymbolAddress((void**)&kbh, g_kbh); cudaGetSymbolAddress((void**)&kbl, g_kbl);
    cudaGetSymbolAddress((void**)&vth, g_vth); cudaGetSymbolAddress((void**)&vtl, g_vtl);

    cudaFuncSetAttribute(gemm_qkv, cudaFuncAttributeMaxDynamicSharedMemorySize, GEMM_SMEM);
    cudaFuncSetAttribute(gemm_pre, cudaFuncAttributeMaxDynamicSharedMemorySize, GEMM_SMEM);
    cudaFuncSetAttribute(flash_tc, cudaFuncAttributeMaxDynamicSharedMemorySize, FL_SMEM);

    // #1: weights transpose + x conversion + rope tables
    prep<<<dim3(64, 64, 6), 256>>>(Wq, Wk, Wv, Wo, x,
                                   wqh, wql, wkh, wkl, wvh, wvl, woh, wol,
                                   xh, xl, ct, st);
    // #2: Q/K/V projections (128x256 tiles)
    gemm_qkv<<<dim3(12, 32), 512, GEMM_SMEM>>>(xh, xl, wqh, wql, wkh, wkl,
                                               wvh, wvl, q, k, v);
    // #3: norm + rope (table) + V transpose
    normropev<<<dim3(MROWS, NH + NKV + 4), 128>>>(q, k, v, qnw, knw, ct, st,
                                                  qbh, qbl, kbh, kbl, vth, vtl);
    // #4: flash attention  (ncu-captured position)
    flash_tc<<<dim3(SEQ / 128, NH, BATCH), 256, FL_SMEM>>>(qbh, qbl, kbh, kbl,
                                                           vth, vtl, aoh, aol);
    // #5: output projection (128x256 tiles)
    gemm_pre<<<dim3(8, 32), 512, GEMM_SMEM>>>(aoh, aol, woh, wol, out, DIM, DIM);
}